// round 12
// baseline (speedup 1.0000x reference)
#include <cuda_runtime.h>
#include <cuda_bf16.h>
#include <math.h>
#include <stdint.h>

// Problem constants
#define BATCH   8
#define HW      128
#define LTOK    16384
#define C       192
#define WS      8
#define SHIFT   4
#define NH      6
#define HD      32
#define NWIN    2048
#define NTOK    131072

// ---------------- scratch (device globals) ---------------------------------
__device__ __nv_bfloat16 g_xw  [(size_t)NTOK * C];
__device__ __nv_bfloat16 g_qkv [(size_t)NTOK * 3 * C];
__device__ float         g_x1  [(size_t)NTOK * C];
__device__ __nv_bfloat16 g_wqkv [C * 3 * C];    // [K,N] bf16
__device__ __nv_bfloat16 g_wproj[C * C];        // [K,N] bf16
__device__ __nv_bfloat16 g_w1   [C * 4 * C];    // [K,N] bf16
__device__ __nv_bfloat16 g_w2   [4 * C * C];    // [K,N] bf16
__device__ float         g_abias[NH * 64 * 64];

// ---------------- helpers --------------------------------------------------
__device__ __forceinline__ uint32_t smem_u32(const void* p) {
    return (uint32_t)__cvta_generic_to_shared(p);
}
__device__ __forceinline__ void cpasync16(uint32_t dst, const void* src) {
    asm volatile("cp.async.cg.shared.global [%0], [%1], 16;" :: "r"(dst), "l"(src));
}
__device__ __forceinline__ void ldsm_x4(uint32_t* r, uint32_t addr) {
    asm volatile("ldmatrix.sync.aligned.m8n8.x4.shared.b16 {%0,%1,%2,%3}, [%4];"
        : "=r"(r[0]), "=r"(r[1]), "=r"(r[2]), "=r"(r[3]) : "r"(addr));
}
__device__ __forceinline__ void ldsm_x4_t(uint32_t* r, uint32_t addr) {
    asm volatile("ldmatrix.sync.aligned.m8n8.x4.trans.shared.b16 {%0,%1,%2,%3}, [%4];"
        : "=r"(r[0]), "=r"(r[1]), "=r"(r[2]), "=r"(r[3]) : "r"(addr));
}
__device__ __forceinline__ void mma_bf16(float* d, const uint32_t* a, const uint32_t* b) {
    asm volatile(
        "mma.sync.aligned.m16n8k16.row.col.f32.bf16.bf16.f32 "
        "{%0,%1,%2,%3}, {%4,%5,%6,%7}, {%8,%9}, {%0,%1,%2,%3};"
        : "+f"(d[0]), "+f"(d[1]), "+f"(d[2]), "+f"(d[3])
        : "r"(a[0]), "r"(a[1]), "r"(a[2]), "r"(a[3]), "r"(b[0]), "r"(b[1]));
}
__device__ __forceinline__ uint32_t packbf(float lo, float hi) {
    uint32_t r;
    asm("cvt.rn.bf16x2.f32 %0, %1, %2;" : "=r"(r) : "f"(hi), "f"(lo));
    return r;
}
__device__ __forceinline__ float fast_exp(float x) {
    float t = fmaxf(x * 1.4426950408889634f, -100.f);
    float z = t + 12582912.f;
    int   ni = __float_as_int(z);
    float nf = z - 12582912.f;
    float f  = t - nf;
    float p = 1.33335581e-3f;
    p = fmaf(p, f, 9.61812910e-3f);
    p = fmaf(p, f, 5.55041087e-2f);
    p = fmaf(p, f, 2.40226507e-1f);
    p = fmaf(p, f, 6.93147181e-1f);
    p = fmaf(p, f, 1.0f);
    float sc = __int_as_float((((ni & 0x7FFFFF) - 0x400000) + 127) << 23);
    return p * sc;
}

// window-row (w*64+n) -> flat token index
__device__ __forceinline__ int win_row_to_tok(int row) {
    int w  = row >> 6;
    int n  = row & 63;
    int b  = w >> 8;
    int wy = (w >> 4) & 15;
    int wx = w & 15;
    int iy = n >> 3;
    int ix = n & 7;
    int hr = (wy * WS + iy + SHIFT) & (HW - 1);
    int wr = (wx * WS + ix + SHIFT) & (HW - 1);
    return (b << 14) + (hr << 7) + wr;
}

// ---------------- merged prep kernel ---------------------------------------
#define SZ_QKVW (C * 3 * C)
#define SZ_PROJ (C * C)
#define SZ_W1   (C * 4 * C)
#define SZ_W2   (4 * C * C)
#define SZ_ALL  (SZ_QKVW + SZ_PROJ + SZ_W1 + SZ_W2)

__global__ __launch_bounds__(256) void prep_w_kernel(const float* __restrict__ qkv_w,
                                                     const float* __restrict__ proj_w,
                                                     const float* __restrict__ w1,
                                                     const float* __restrict__ w2,
                                                     __nv_bfloat16* __restrict__ wqkv,
                                                     __nv_bfloat16* __restrict__ wproj,
                                                     __nv_bfloat16* __restrict__ ow1,
                                                     __nv_bfloat16* __restrict__ ow2) {
    int i = blockIdx.x * 256 + threadIdx.x;
    if (i >= SZ_ALL) return;
    if (i < SZ_QKVW) {
        wqkv[i] = __float2bfloat16(qkv_w[i]);
    } else if (i < SZ_QKVW + SZ_PROJ) {
        int j = i - SZ_QKVW;
        wproj[j] = __float2bfloat16(proj_w[j]);
    } else if (i < SZ_QKVW + SZ_PROJ + SZ_W1) {
        int j = i - SZ_QKVW - SZ_PROJ;
        ow1[j] = __float2bfloat16(w1[j]);
    } else {
        int j = i - SZ_QKVW - SZ_PROJ - SZ_W1;
        ow2[j] = __float2bfloat16(w2[j]);
    }
}
__global__ void abias_kernel(const float* __restrict__ rpb, float* __restrict__ tab) {
    int i = blockIdx.x * 256 + threadIdx.x;
    if (i >= NH * 64 * 64) return;
    int h = i >> 12;
    int n = (i >> 6) & 63;
    int m = i & 63;
    int iy = n >> 3, ix = n & 7, jy = m >> 3, jx = m & 7;
    int ridx = (iy - jy + 7) * 15 + (ix - jx + 7);
    tab[i] = rpb[ridx * NH + h];
}

// ---------------- LayerNorm1 (gathered) -> bf16, vectorized ----------------
__global__ __launch_bounds__(256) void ln_kernel(const float* __restrict__ x,
                                                 const float* __restrict__ s,
                                                 const float* __restrict__ b,
                                                 __nv_bfloat16* __restrict__ out) {
    int warp = threadIdx.x >> 5;
    int lane = threadIdx.x & 31;
    int row  = blockIdx.x * 8 + warp;
    int src  = win_row_to_tok(row);
    const float2* xp = (const float2*)(x + (size_t)src * C);
    const float2* sp = (const float2*)s;
    const float2* bp = (const float2*)b;

    float2 v[3];
    float sum = 0.f, sq = 0.f;
#pragma unroll
    for (int i = 0; i < 3; i++) {
        v[i] = xp[lane + i * 32];
        sum += v[i].x + v[i].y;
        sq  += v[i].x * v[i].x + v[i].y * v[i].y;
    }
#pragma unroll
    for (int o = 16; o > 0; o >>= 1) {
        sum += __shfl_xor_sync(0xffffffffu, sum, o);
        sq  += __shfl_xor_sync(0xffffffffu, sq, o);
    }
    float mean = sum * (1.f / C);
    float var  = sq * (1.f / C) - mean * mean;
    float rstd = rsqrtf(var + 1e-5f);

    uint32_t* op = (uint32_t*)(out + (size_t)row * C);
#pragma unroll
    for (int i = 0; i < 3; i++) {
        int c2 = lane + i * 32;
        float2 sv = sp[c2], bv = bp[c2];
        op[c2] = packbf((v[i].x - mean) * rstd * sv.x + bv.x,
                        (v[i].y - mean) * rstd * sv.y + bv.y);
    }
}

// ---------------- bf16 MMA GEMM for QKV: R9 proven (256x64, 3-stage) -------
#define GBM 256
#define GBN 64
#define GBK 32
#define QKV_SMEM (3 * (GBM * GBK + GBK * GBN) * 2)   // 61440

__global__ __launch_bounds__(256, 2) void qkv_gemm(const __nv_bfloat16* __restrict__ A,
                                                   const __nv_bfloat16* __restrict__ Bm,
                                                   const float* __restrict__ bias,
                                                   __nv_bfloat16* __restrict__ out,
                                                   int M, int N, int K) {
    extern __shared__ char qsm[];
    uint32_t sa = smem_u32(qsm);
    uint32_t sb = sa + 3 * GBM * GBK * 2;

    int tid  = threadIdx.x;
    int wid  = tid >> 5, lane = tid & 31;
    int wm   = (wid & 3) * 64;
    int wn   = (wid >> 2) * 32;
    int m0   = blockIdx.y * GBM;
    int n0   = blockIdx.x * GBN;

    uint32_t aoff[4][2], boff[2][2];
#pragma unroll
    for (int ma = 0; ma < 4; ma++)
#pragma unroll
        for (int ks = 0; ks < 2; ks++) {
            int row = wm + ma * 16 + (lane & 7) + 8 * ((lane >> 3) & 1);
            int ch  = 2 * ks + (lane >> 4);
            aoff[ma][ks] = row * 64 + ((ch ^ ((row >> 1) & 3)) << 4);
        }
#pragma unroll
    for (int np = 0; np < 2; np++)
#pragma unroll
        for (int ks = 0; ks < 2; ks++) {
            int k  = ks * 16 + (lane & 7) + 8 * ((lane >> 3) & 1);
            int cn = (wn >> 3) + np * 2 + (lane >> 4);
            boff[np][ks] = k * 128 + ((cn ^ (k & 7)) << 4);
        }

    float acc[4][4][4];
#pragma unroll
    for (int i = 0; i < 4; i++)
#pragma unroll
        for (int j = 0; j < 4; j++)
#pragma unroll
            for (int q = 0; q < 4; q++) acc[i][j][q] = 0.f;

    const int nk = K / GBK;
    int arow = tid >> 2, ac = tid & 3;
    int bk = tid >> 3,  bcn = tid & 7;
    uint32_t adst0 = arow * 64 + ((ac ^ ((arow >> 1) & 3)) << 4);
    uint32_t bdst  = bk * 128 + ((bcn ^ (bk & 7)) << 4);

    auto issue = [&](int kt, int buf) {
        const __nv_bfloat16* ga = A + (size_t)m0 * K + kt * GBK + ac * 8;
#pragma unroll
        for (int p = 0; p < 4; p++) {
            int row = arow + p * 64;
            cpasync16(sa + buf * (GBM * GBK * 2) + adst0 + p * 4096,
                      ga + (size_t)row * K);
        }
        cpasync16(sb + buf * (GBK * GBN * 2) + bdst,
                  Bm + (size_t)(kt * GBK + bk) * N + n0 + bcn * 8);
        asm volatile("cp.async.commit_group;" ::: "memory");
    };

    issue(0, 0);
    issue(1, 1);
    for (int kt = 0; kt < nk; kt++) {
        if (kt < nk - 1) {
            asm volatile("cp.async.wait_group 1;" ::: "memory");
        } else {
            asm volatile("cp.async.wait_group 0;" ::: "memory");
        }
        __syncthreads();

        int buf = kt % 3;
        uint32_t ab = sa + buf * (GBM * GBK * 2);
        uint32_t bb = sb + buf * (GBK * GBN * 2);
#pragma unroll
        for (int ks = 0; ks < 2; ks++) {
            uint32_t af[4][4], bfr[4][2];
#pragma unroll
            for (int ma = 0; ma < 4; ma++) ldsm_x4(af[ma], ab + aoff[ma][ks]);
#pragma unroll
            for (int np = 0; np < 2; np++) {
                uint32_t t4[4];
                ldsm_x4_t(t4, bb + boff[np][ks]);
                bfr[np * 2][0] = t4[0]; bfr[np * 2][1] = t4[1];
                bfr[np * 2 + 1][0] = t4[2]; bfr[np * 2 + 1][1] = t4[3];
            }
#pragma unroll
            for (int ma = 0; ma < 4; ma++)
#pragma unroll
                for (int nb = 0; nb < 4; nb++)
                    mma_bf16(acc[ma][nb], af[ma], bfr[nb]);
        }
        if (kt + 2 < nk) issue(kt + 2, (kt + 2) % 3);
    }

    int g = lane >> 2, tig = lane & 3;
#pragma unroll
    for (int ma = 0; ma < 4; ma++) {
        int rlo = m0 + wm + ma * 16 + g;
        int rhi = rlo + 8;
#pragma unroll
        for (int nb = 0; nb < 4; nb++) {
            int col = n0 + wn + nb * 8 + tig * 2;
            float bi0 = bias[col], bi1 = bias[col + 1];
            *(uint32_t*)&out[(size_t)rlo * N + col] = packbf(acc[ma][nb][0] + bi0, acc[ma][nb][1] + bi1);
            *(uint32_t*)&out[(size_t)rhi * N + col] = packbf(acc[ma][nb][2] + bi0, acc[ma][nb][3] + bi1);
        }
    }
}

// ---------------- attention + proj + residual -> x1 (R10, frozen) ----------
#define MK_SMEM 221184

__global__ __launch_bounds__(512) void attnproj_kernel(const __nv_bfloat16* __restrict__ qkv,
                                                       const float* __restrict__ abias,
                                                       const __nv_bfloat16* __restrict__ wproj,
                                                       const float* __restrict__ pbias,
                                                       const float* __restrict__ x,
                                                       float* __restrict__ x1) {
    extern __shared__ char sm[];
    uint32_t sq  = smem_u32(sm);
    uint32_t skb = sq + 49152;
    uint32_t svb = sq + 98304;
    uint32_t sab = sq + 147456;
    uint32_t swb = sq + 196608;
    char* sA_p = sm + 147456;

    int tid  = threadIdx.x;
    int wid  = tid >> 5, lane = tid & 31;
    int m0   = blockIdx.x * 128;
    int g = lane >> 2, q2 = (lane & 3) * 2;

    auto issueW = [&](int s, int buf) {
#pragma unroll
        for (int j = 0; j < 2; j++) {
            int i = tid + j * 512;
            if (i < 768) {
                int kl = i / 24, ch = i % 24;
                cpasync16(swb + buf * 12288 + kl * 384 + ((ch ^ (kl & 7)) << 4),
                          wproj + (size_t)(s * 32 + kl) * 192 + ch * 8);
            }
        }
        asm volatile("cp.async.commit_group;" ::: "memory");
    };

#pragma unroll
    for (int j = 0; j < 18; j++) {
        int i = tid + j * 512;
        int t = i / 72, cc = i % 72;
        int mat = cc / 24, ch = cc % 24;
        int win = t >> 6, r = t & 63;
        cpasync16(sq + mat * 49152 + win * 24576 + r * 384 + ((ch ^ (r & 7)) << 4),
                  qkv + (size_t)(m0 + t) * 576 + cc * 8);
    }
    asm volatile("cp.async.commit_group;" ::: "memory");
    issueW(0, 0);
    asm volatile("cp.async.wait_group 1;" ::: "memory");
    __syncthreads();

#pragma unroll
    for (int it = 0; it < 3; it++) {
        int tk  = wid + it * 16;
        int win = tk / 24;
        int rem = tk - win * 24;
        int hh  = rem >> 2;
        int r4  = rem & 3;
        int r0  = r4 * 16;

        uint32_t qbase = sq  + win * 24576;
        uint32_t kbase = skb + win * 24576;
        uint32_t vbase = svb + win * 24576;

        float sacc[8][4];
#pragma unroll
        for (int i = 0; i < 8; i++)
#pragma unroll
            for (int q = 0; q < 4; q++) sacc[i][q] = 0.f;

        uint32_t qa[2][4];
#pragma unroll
        for (int ks = 0; ks < 2; ks++) {
            int row = r0 + (lane & 7) + 8 * ((lane >> 3) & 1);
            int ch  = hh * 4 + 2 * ks + (lane >> 4);
            ldsm_x4(qa[ks], qbase + row * 384 + ((ch ^ (row & 7)) << 4));
        }
#pragma unroll
        for (int ks = 0; ks < 2; ks++) {
#pragma unroll
            for (int np = 0; np < 4; np++) {
                int tok = np * 16 + (lane & 7) + 8 * (lane >> 4);
                int ch  = hh * 4 + 2 * ks + ((lane >> 3) & 1);
                uint32_t kb[4];
                ldsm_x4(kb, kbase + tok * 384 + ((ch ^ (tok & 7)) << 4));
                mma_bf16(sacc[2 * np],     qa[ks], kb);
                mma_bf16(sacc[2 * np + 1], qa[ks], kb + 2);
            }
        }

        const float scale = 0.17677669529663687f;
        int row0 = r0 + g;
        const float* bt = abias + ((size_t)hh * 64) * 64;
        float mx0 = -1e30f, mx1 = -1e30f;
#pragma unroll
        for (int nb = 0; nb < 8; nb++) {
            int mcol = nb * 8 + q2;
            const float* b0 = bt + row0 * 64 + mcol;
            const float* b1 = b0 + 8 * 64;
            sacc[nb][0] = fmaf(sacc[nb][0], scale, b0[0]);
            sacc[nb][1] = fmaf(sacc[nb][1], scale, b0[1]);
            sacc[nb][2] = fmaf(sacc[nb][2], scale, b1[0]);
            sacc[nb][3] = fmaf(sacc[nb][3], scale, b1[1]);
            mx0 = fmaxf(mx0, fmaxf(sacc[nb][0], sacc[nb][1]));
            mx1 = fmaxf(mx1, fmaxf(sacc[nb][2], sacc[nb][3]));
        }
#pragma unroll
        for (int o = 1; o < 4; o <<= 1) {
            mx0 = fmaxf(mx0, __shfl_xor_sync(0xffffffffu, mx0, o));
            mx1 = fmaxf(mx1, __shfl_xor_sync(0xffffffffu, mx1, o));
        }
        float sum0 = 0.f, sum1 = 0.f;
#pragma unroll
        for (int nb = 0; nb < 8; nb++) {
            sacc[nb][0] = fast_exp(sacc[nb][0] - mx0);
            sacc[nb][1] = fast_exp(sacc[nb][1] - mx0);
            sacc[nb][2] = fast_exp(sacc[nb][2] - mx1);
            sacc[nb][3] = fast_exp(sacc[nb][3] - mx1);
            sum0 += sacc[nb][0] + sacc[nb][1];
            sum1 += sacc[nb][2] + sacc[nb][3];
        }
#pragma unroll
        for (int o = 1; o < 4; o <<= 1) {
            sum0 += __shfl_xor_sync(0xffffffffu, sum0, o);
            sum1 += __shfl_xor_sync(0xffffffffu, sum1, o);
        }

        uint32_t pa[4][4];
#pragma unroll
        for (int ks = 0; ks < 4; ks++) {
            pa[ks][0] = packbf(sacc[2 * ks][0],     sacc[2 * ks][1]);
            pa[ks][1] = packbf(sacc[2 * ks][2],     sacc[2 * ks][3]);
            pa[ks][2] = packbf(sacc[2 * ks + 1][0], sacc[2 * ks + 1][1]);
            pa[ks][3] = packbf(sacc[2 * ks + 1][2], sacc[2 * ks + 1][3]);
        }

        float oacc[4][4];
#pragma unroll
        for (int i = 0; i < 4; i++)
#pragma unroll
            for (int q = 0; q < 4; q++) oacc[i][q] = 0.f;
#pragma unroll
        for (int ks = 0; ks < 4; ks++) {
#pragma unroll
            for (int np = 0; np < 2; np++) {
                int kr = ks * 16 + (lane & 7) + 8 * ((lane >> 3) & 1);
                int cn = hh * 4 + np * 2 + (lane >> 4);
                uint32_t vb[4];
                ldsm_x4_t(vb, vbase + kr * 384 + ((cn ^ (kr & 7)) << 4));
                mma_bf16(oacc[2 * np],     pa[ks], vb);
                mma_bf16(oacc[2 * np + 1], pa[ks], vb + 2);
            }
        }

        float inv0 = 1.f / sum0, inv1 = 1.f / sum1;
        int rl = win * 64 + row0;
        int rh = rl + 8;
#pragma unroll
        for (int nb = 0; nb < 4; nb++) {
            int chA = hh * 4 + nb;
            *(uint32_t*)(sA_p + rl * 384 + ((chA ^ (rl & 7)) << 4) + q2 * 2) =
                packbf(oacc[nb][0] * inv0, oacc[nb][1] * inv0);
            *(uint32_t*)(sA_p + rh * 384 + ((chA ^ (rh & 7)) << 4) + q2 * 2) =
                packbf(oacc[nb][2] * inv1, oacc[nb][3] * inv1);
        }
    }
    __syncthreads();

    int wm = (wid & 3) * 32;
    int wn = (wid >> 2) * 48;
    float acc[2][6][4];
#pragma unroll
    for (int i = 0; i < 2; i++)
#pragma unroll
        for (int j = 0; j < 6; j++)
#pragma unroll
            for (int q = 0; q < 4; q++) acc[i][j][q] = 0.f;

    for (int s = 0; s < 6; s++) {
        if (s < 5) {
            issueW(s + 1, (s + 1) & 1);
            asm volatile("cp.async.wait_group 1;" ::: "memory");
        } else {
            asm volatile("cp.async.wait_group 0;" ::: "memory");
        }
        __syncthreads();
        uint32_t bb = swb + (s & 1) * 12288;
#pragma unroll
        for (int t = 0; t < 2; t++) {
            uint32_t af[2][4];
#pragma unroll
            for (int fi = 0; fi < 2; fi++) {
                int row = wm + fi * 16 + (lane & 7) + 8 * ((lane >> 3) & 1);
                int ch  = 4 * s + 2 * t + (lane >> 4);
                ldsm_x4(af[fi], sab + row * 384 + ((ch ^ (row & 7)) << 4));
            }
            uint32_t bfr[6][2];
#pragma unroll
            for (int j = 0; j < 3; j++) {
                int kl = t * 16 + (lane & 7) + 8 * ((lane >> 3) & 1);
                int cn = (wn >> 3) + 2 * j + (lane >> 4);
                uint32_t t4[4];
                ldsm_x4_t(t4, bb + kl * 384 + ((cn ^ (kl & 7)) << 4));
                bfr[2 * j][0] = t4[0]; bfr[2 * j][1] = t4[1];
                bfr[2 * j + 1][0] = t4[2]; bfr[2 * j + 1][1] = t4[3];
            }
#pragma unroll
            for (int fi = 0; fi < 2; fi++)
#pragma unroll
                for (int nj = 0; nj < 6; nj++)
                    mma_bf16(acc[fi][nj], af[fi], bfr[nj]);
        }
        __syncthreads();
    }

#pragma unroll
    for (int fi = 0; fi < 2; fi++) {
        int rl = wm + fi * 16 + g;
        int rh = rl + 8;
        int tokl = win_row_to_tok(m0 + rl);
        int tokh = win_row_to_tok(m0 + rh);
#pragma unroll
        for (int nj = 0; nj < 6; nj++) {
            int col = wn + nj * 8 + q2;
            float bi0 = pbias[col], bi1 = pbias[col + 1];
            float2 xl = *(const float2*)&x[(size_t)tokl * C + col];
            float2 xh = *(const float2*)&x[(size_t)tokh * C + col];
            *(float2*)&x1[(size_t)tokl * C + col] =
                make_float2(acc[fi][nj][0] + bi0 + xl.x, acc[fi][nj][1] + bi1 + xl.y);
            *(float2*)&x1[(size_t)tokh * C + col] =
                make_float2(acc[fi][nj][2] + bi0 + xh.x, acc[fi][nj][3] + bi1 + xh.y);
        }
    }
}

// ---------------- fused MLP + LN2: continuous 48-stage W pipeline ----------
// smem: sX1 fp32 128x196 [0,100352) ; sXn bf16 [100352,149504) ;
//       sH [149504,198656) ; sW 2x12288 [198656,223232)
#define MLP_SMEM 223232
#define X1W 196

__global__ __launch_bounds__(512) void mlp_kernel(const float* __restrict__ x1,
                                                  const float* __restrict__ n2s,
                                                  const float* __restrict__ n2b,
                                                  const __nv_bfloat16* __restrict__ w1,
                                                  const float* __restrict__ b1,
                                                  const __nv_bfloat16* __restrict__ w2,
                                                  const float* __restrict__ b2,
                                                  float* __restrict__ out) {
    extern __shared__ char sm[];
    float* sX1 = (float*)sm;
    char* sXn_p = sm + 100352;
    char* sH_p  = sm + 149504;
    uint32_t sx1b = smem_u32(sm);
    uint32_t sxn  = sx1b + 100352;
    uint32_t shb  = sx1b + 149504;
    uint32_t sbb  = sx1b + 198656;

    int tid = threadIdx.x;
    int wid = tid >> 5, lane = tid & 31;
    int m0 = blockIdx.x * 128;
    int wm = (wid & 3) * 32;
    int wn = (wid >> 2) * 48;
    int g = lane >> 2, q2 = (lane & 3) * 2;

    // flat W stage issue: f in [0,48). f -> chunk c=f/12, phase=(f%12)/6, s6=f%6
    auto issueF = [&](int f) {
        int cc_ = f / 12;
        int ph_ = (f % 12) / 6;
        int s6  = f % 6;
        const __nv_bfloat16* Wg = ph_ ? w2 : w1;
        int rstride = ph_ ? C : 4 * C;
        int rowb    = ph_ ? (cc_ * 192 + s6 * 32) : (s6 * 32);
        int coloff  = ph_ ? 0 : cc_ * 192;
#pragma unroll
        for (int j = 0; j < 2; j++) {
            int i = tid + j * 512;
            if (i < 768) {
                int kl = i / 24, cch = i % 24;
                cpasync16(sbb + (f & 1) * 12288 + kl * 384 + ((cch ^ (kl & 7)) << 4),
                          Wg + (size_t)(rowb + kl) * rstride + coloff + cch * 8);
            }
        }
        asm volatile("cp.async.commit_group;" ::: "memory");
    };

    // load x1 tile fp32
#pragma unroll
    for (int j = 0; j < 12; j++) {
        int i = tid + j * 512;
        int r = i / 48, cc = i % 48;
        cpasync16(sx1b + r * (X1W * 4) + cc * 16, x1 + (size_t)(m0 + r) * C + cc * 4);
    }
    asm volatile("cp.async.commit_group;" ::: "memory");
    issueF(0);                                           // overlap W stage 0 with LN
    asm volatile("cp.async.wait_group 1;" ::: "memory"); // x1 tile ready
    __syncthreads();

    // LN2
    {
        const float2* sp = (const float2*)n2s;
        const float2* bp = (const float2*)n2b;
        float2 sg[3], bg[3];
#pragma unroll
        for (int i = 0; i < 3; i++) {
            sg[i] = sp[lane + i * 32];
            bg[i] = bp[lane + i * 32];
        }
#pragma unroll
        for (int rr = 0; rr < 8; rr++) {
            int row = wid * 8 + rr;
            const float2* rp = (const float2*)(sX1 + row * X1W);
            float2 v[3];
            float sum = 0.f, sq = 0.f;
#pragma unroll
            for (int i = 0; i < 3; i++) {
                v[i] = rp[lane + i * 32];
                sum += v[i].x + v[i].y;
                sq  += v[i].x * v[i].x + v[i].y * v[i].y;
            }
#pragma unroll
            for (int o = 16; o > 0; o >>= 1) {
                sum += __shfl_xor_sync(0xffffffffu, sum, o);
                sq  += __shfl_xor_sync(0xffffffffu, sq, o);
            }
            float mean = sum * (1.f / C);
            float var  = sq * (1.f / C) - mean * mean;
            float rstd = rsqrtf(var + 1e-5f);
#pragma unroll
            for (int i = 0; i < 3; i++) {
                int c2 = lane + i * 32;
                uint32_t val = packbf((v[i].x - mean) * rstd * sg[i].x + bg[i].x,
                                      (v[i].y - mean) * rstd * sg[i].y + bg[i].y);
                int ch = c2 >> 2;
                *(uint32_t*)(sXn_p + row * 384 + ((ch ^ (row & 7)) << 4) + (c2 & 3) * 4) = val;
            }
        }
    }
    __syncthreads();

    // one stage of compute: aBase/bb/kk fixed, mma into acc
    auto doStage = [&](float (&acc)[2][6][4], uint32_t aBase, uint32_t bb, int s6) {
#pragma unroll
        for (int t = 0; t < 2; t++) {
            int kk = s6 * 2 + t;
            uint32_t af[2][4];
#pragma unroll
            for (int fi = 0; fi < 2; fi++) {
                int row = wm + fi * 16 + (lane & 7) + 8 * ((lane >> 3) & 1);
                int ch  = 2 * kk + (lane >> 4);
                ldsm_x4(af[fi], aBase + row * 384 + ((ch ^ (row & 7)) << 4));
            }
            uint32_t bfr[6][2];
#pragma unroll
            for (int j = 0; j < 3; j++) {
                int kl = t * 16 + (lane & 7) + 8 * ((lane >> 3) & 1);
                int cn = (wn >> 3) + 2 * j + (lane >> 4);
                uint32_t t4[4];
                ldsm_x4_t(t4, bb + kl * 384 + ((cn ^ (kl & 7)) << 4));
                bfr[2 * j][0] = t4[0]; bfr[2 * j][1] = t4[1];
                bfr[2 * j + 1][0] = t4[2]; bfr[2 * j + 1][1] = t4[3];
            }
#pragma unroll
            for (int fi = 0; fi < 2; fi++)
#pragma unroll
                for (int nj = 0; nj < 6; nj++)
                    mma_bf16(acc[fi][nj], af[fi], bfr[nj]);
        }
    };

    float acc2[2][6][4];
#pragma unroll
    for (int i = 0; i < 2; i++)
#pragma unroll
        for (int j = 0; j < 6; j++)
#pragma unroll
            for (int q = 0; q < 4; q++) acc2[i][j][q] = 0.f;

    float acc1[2][6][4];
    const float is2 = 0.70710678118654752f;

    for (int g8 = 0; g8 < 8; g8++) {
        int ph = g8 & 1;
        int cc = g8 >> 1;
        uint32_t aBase = ph ? shb : sxn;
        if (!ph) {
#pragma unroll
            for (int i = 0; i < 2; i++)
#pragma unroll
                for (int j = 0; j < 6; j++)
#pragma unroll
                    for (int q = 0; q < 4; q++) acc1[i][j][q] = 0.f;
        }

        for (int s = 0; s < 6; s++) {
            int f = g8 * 6 + s;
            if (f + 1 < 48) {
                issueF(f + 1);
                asm volatile("cp.async.wait_group 1;" ::: "memory");
            } else {
                asm volatile("cp.async.wait_group 0;" ::: "memory");
            }
            __syncthreads();
            uint32_t bb = sbb + (f & 1) * 12288;
            if (ph) doStage(acc2, aBase, bb, s);
            else    doStage(acc1, aBase, bb, s);
        }

        if (!ph) {
            // GELU epilogue -> sH (GEMM2 of this chunk reads it)
            __syncthreads();   // all warps done reading previous sH (chunk cc-1 GEMM2)
#pragma unroll
            for (int fi = 0; fi < 2; fi++) {
                int rl = wm + fi * 16 + g;
                int rh = rl + 8;
#pragma unroll
                for (int nj = 0; nj < 6; nj++) {
                    int colL = wn + nj * 8 + q2;
                    int gcol = cc * 192 + colL;
                    float bi0 = b1[gcol], bi1 = b1[gcol + 1];
                    float v00 = acc1[fi][nj][0] + bi0;
                    float v01 = acc1[fi][nj][1] + bi1;
                    float v10 = acc1[fi][nj][2] + bi0;
                    float v11 = acc1[fi][nj][3] + bi1;
                    v00 = 0.5f * v00 * (1.f + erff(v00 * is2));
                    v01 = 0.5f * v01 * (1.f + erff(v01 * is2));
                    v10 = 0.5f * v10 * (1.f + erff(v10 * is2));
                    v11 = 0.5f * v11 * (1.f + erff(v11 * is2));
                    int chh = colL >> 3;
                    *(uint32_t*)(sH_p + rl * 384 + ((chh ^ (rl & 7)) << 4) + q2 * 2) = packbf(v00, v01);
                    *(uint32_t*)(sH_p + rh * 384 + ((chh ^ (rh & 7)) << 4) + q2 * 2) = packbf(v10, v11);
                }
            }
            __syncthreads();   // sH visible before GEMM2
        }
    }

    // epilogue: + b2 + residual (from smem x1 tile) -> fp32 out
#pragma unroll
    for (int fi = 0; fi < 2; fi++) {
        int rl = wm + fi * 16 + g;
        int rh = rl + 8;
        int ml = m0 + rl, mh = m0 + rh;
#pragma unroll
        for (int nj = 0; nj < 6; nj++) {
            int col = wn + nj * 8 + q2;
            float bi0 = b2[col], bi1 = b2[col + 1];
            float xl0 = sX1[rl * X1W + col],     xl1 = sX1[rl * X1W + col + 1];
            float xh0 = sX1[rh * X1W + col],     xh1 = sX1[rh * X1W + col + 1];
            *(float2*)&out[(size_t)ml * C + col] =
                make_float2(acc2[fi][nj][0] + bi0 + xl0, acc2[fi][nj][1] + bi1 + xl1);
            *(float2*)&out[(size_t)mh * C + col] =
                make_float2(acc2[fi][nj][2] + bi0 + xh0, acc2[fi][nj][3] + bi1 + xh1);
        }
    }
}

// ---------------- launch ---------------------------------------------------
extern "C" void kernel_launch(void* const* d_in, const int* in_sizes, int n_in,
                              void* d_out, int out_size) {
    const float* x      = (const float*)d_in[0];
    const float* qkv_w  = (const float*)d_in[1];
    const float* qkv_b  = (const float*)d_in[2];
    const float* proj_w = (const float*)d_in[3];
    const float* proj_b = (const float*)d_in[4];
    const float* rpb    = (const float*)d_in[5];
    const float* n1s    = (const float*)d_in[6];
    const float* n1b    = (const float*)d_in[7];
    const float* n2s    = (const float*)d_in[8];
    const float* n2b    = (const float*)d_in[9];
    const float* w1     = (const float*)d_in[10];
    const float* b1     = (const float*)d_in[11];
    const float* w2     = (const float*)d_in[12];
    const float* b2     = (const float*)d_in[13];
    float* out = (float*)d_out;

    __nv_bfloat16 *xw, *qkv, *wqkv, *wproj, *ww1, *ww2;
    float *x1, *abias;
    cudaGetSymbolAddress((void**)&xw,    g_xw);
    cudaGetSymbolAddress((void**)&qkv,   g_qkv);
    cudaGetSymbolAddress((void**)&x1,    g_x1);
    cudaGetSymbolAddress((void**)&wqkv,  g_wqkv);
    cudaGetSymbolAddress((void**)&wproj, g_wproj);
    cudaGetSymbolAddress((void**)&ww1,   g_w1);
    cudaGetSymbolAddress((void**)&ww2,   g_w2);
    cudaGetSymbolAddress((void**)&abias, g_abias);

    cudaFuncSetAttribute(qkv_gemm,        cudaFuncAttributeMaxDynamicSharedMemorySize, QKV_SMEM);
    cudaFuncSetAttribute(attnproj_kernel, cudaFuncAttributeMaxDynamicSharedMemorySize, MK_SMEM);
    cudaFuncSetAttribute(mlp_kernel,      cudaFuncAttributeMaxDynamicSharedMemorySize, MLP_SMEM);

    // prep
    prep_w_kernel<<<(SZ_ALL + 255) / 256, 256>>>(qkv_w, proj_w, w1, w2,
                                                 wqkv, wproj, ww1, ww2);
    abias_kernel<<<(NH * 64 * 64 + 255) / 256, 256>>>(rpb, abias);

    // 1. LN1 + shift + window gather -> bf16
    ln_kernel<<<NTOK / 8, 256>>>(x, n1s, n1b, xw);

    // 2. QKV GEMM -> bf16 (R9 proven shape)
    qkv_gemm<<<dim3((3 * C) / GBN, NTOK / GBM), 256, QKV_SMEM>>>(xw, wqkv, qkv_b, qkv,
                                                                 NTOK, 3 * C, C);

    // 3. attention + proj + residual -> x1 (fp32, token order)
    attnproj_kernel<<<NTOK / 128, 512, MK_SMEM>>>(qkv, abias, wproj, proj_b, x, x1);

    // 4. fused LN2 + MLP + residual -> out (continuous W pipeline)
    mlp_kernel<<<NTOK / 128, 512, MLP_SMEM>>>(x1, n2s, n2b, ww1, b1, ww2, b2, out);
}

// round 13
// speedup vs baseline: 1.1489x; 1.1489x over previous
#include <cuda_runtime.h>
#include <cuda_bf16.h>
#include <math.h>
#include <stdint.h>

// Problem constants
#define BATCH   8
#define HW      128
#define LTOK    16384
#define C       192
#define WS      8
#define SHIFT   4
#define NH      6
#define HD      32
#define NWIN    2048
#define NTOK    131072

// ---------------- scratch (device globals) ---------------------------------
__device__ __nv_bfloat16 g_xw  [(size_t)NTOK * C];
__device__ __nv_bfloat16 g_qkv [(size_t)NTOK * 3 * C];
__device__ float         g_x1  [(size_t)NTOK * C];
__device__ __nv_bfloat16 g_wqkv [C * 3 * C];    // [K,N] bf16
__device__ __nv_bfloat16 g_wproj[C * C];        // [K,N] bf16
__device__ __nv_bfloat16 g_w1   [C * 4 * C];    // [K,N] bf16
__device__ __nv_bfloat16 g_w2   [4 * C * C];    // [K,N] bf16
__device__ float         g_abias[NH * 64 * 64];

// ---------------- helpers --------------------------------------------------
__device__ __forceinline__ uint32_t smem_u32(const void* p) {
    return (uint32_t)__cvta_generic_to_shared(p);
}
__device__ __forceinline__ void cpasync16(uint32_t dst, const void* src) {
    asm volatile("cp.async.cg.shared.global [%0], [%1], 16;" :: "r"(dst), "l"(src));
}
__device__ __forceinline__ void ldsm_x4(uint32_t* r, uint32_t addr) {
    asm volatile("ldmatrix.sync.aligned.m8n8.x4.shared.b16 {%0,%1,%2,%3}, [%4];"
        : "=r"(r[0]), "=r"(r[1]), "=r"(r[2]), "=r"(r[3]) : "r"(addr));
}
__device__ __forceinline__ void ldsm_x4_t(uint32_t* r, uint32_t addr) {
    asm volatile("ldmatrix.sync.aligned.m8n8.x4.trans.shared.b16 {%0,%1,%2,%3}, [%4];"
        : "=r"(r[0]), "=r"(r[1]), "=r"(r[2]), "=r"(r[3]) : "r"(addr));
}
__device__ __forceinline__ void mma_bf16(float* d, const uint32_t* a, const uint32_t* b) {
    asm volatile(
        "mma.sync.aligned.m16n8k16.row.col.f32.bf16.bf16.f32 "
        "{%0,%1,%2,%3}, {%4,%5,%6,%7}, {%8,%9}, {%0,%1,%2,%3};"
        : "+f"(d[0]), "+f"(d[1]), "+f"(d[2]), "+f"(d[3])
        : "r"(a[0]), "r"(a[1]), "r"(a[2]), "r"(a[3]), "r"(b[0]), "r"(b[1]));
}
__device__ __forceinline__ uint32_t packbf(float lo, float hi) {
    uint32_t r;
    asm("cvt.rn.bf16x2.f32 %0, %1, %2;" : "=r"(r) : "f"(hi), "f"(lo));
    return r;
}
__device__ __forceinline__ float fast_exp(float x) {
    float t = fmaxf(x * 1.4426950408889634f, -100.f);
    float z = t + 12582912.f;
    int   ni = __float_as_int(z);
    float nf = z - 12582912.f;
    float f  = t - nf;
    float p = 1.33335581e-3f;
    p = fmaf(p, f, 9.61812910e-3f);
    p = fmaf(p, f, 5.55041087e-2f);
    p = fmaf(p, f, 2.40226507e-1f);
    p = fmaf(p, f, 6.93147181e-1f);
    p = fmaf(p, f, 1.0f);
    float sc = __int_as_float((((ni & 0x7FFFFF) - 0x400000) + 127) << 23);
    return p * sc;
}

// window-row (w*64+n) -> flat token index
__device__ __forceinline__ int win_row_to_tok(int row) {
    int w  = row >> 6;
    int n  = row & 63;
    int b  = w >> 8;
    int wy = (w >> 4) & 15;
    int wx = w & 15;
    int iy = n >> 3;
    int ix = n & 7;
    int hr = (wy * WS + iy + SHIFT) & (HW - 1);
    int wr = (wx * WS + ix + SHIFT) & (HW - 1);
    return (b << 14) + (hr << 7) + wr;
}

// ---------------- merged prep kernel (weights + abias) ----------------------
#define SZ_QKVW (C * 3 * C)
#define SZ_PROJ (C * C)
#define SZ_W1   (C * 4 * C)
#define SZ_W2   (4 * C * C)
#define SZ_WALL (SZ_QKVW + SZ_PROJ + SZ_W1 + SZ_W2)
#define SZ_AB   (NH * 64 * 64)
#define SZ_ALL  (SZ_WALL + SZ_AB)

__global__ __launch_bounds__(256) void prep_kernel(const float* __restrict__ qkv_w,
                                                   const float* __restrict__ proj_w,
                                                   const float* __restrict__ w1,
                                                   const float* __restrict__ w2,
                                                   const float* __restrict__ rpb,
                                                   __nv_bfloat16* __restrict__ wqkv,
                                                   __nv_bfloat16* __restrict__ wproj,
                                                   __nv_bfloat16* __restrict__ ow1,
                                                   __nv_bfloat16* __restrict__ ow2,
                                                   float* __restrict__ abias) {
    int i = blockIdx.x * 256 + threadIdx.x;
    if (i >= SZ_ALL) return;
    if (i < SZ_QKVW) {
        wqkv[i] = __float2bfloat16(qkv_w[i]);
    } else if (i < SZ_QKVW + SZ_PROJ) {
        int j = i - SZ_QKVW;
        wproj[j] = __float2bfloat16(proj_w[j]);
    } else if (i < SZ_QKVW + SZ_PROJ + SZ_W1) {
        int j = i - SZ_QKVW - SZ_PROJ;
        ow1[j] = __float2bfloat16(w1[j]);
    } else if (i < SZ_WALL) {
        int j = i - SZ_QKVW - SZ_PROJ - SZ_W1;
        ow2[j] = __float2bfloat16(w2[j]);
    } else {
        int j = i - SZ_WALL;
        int h = j >> 12;
        int n = (j >> 6) & 63;
        int m = j & 63;
        int iy = n >> 3, ix = n & 7, jy = m >> 3, jx = m & 7;
        int ridx = (iy - jy + 7) * 15 + (ix - jx + 7);
        abias[j] = rpb[ridx * NH + h];
    }
}

// ---------------- LayerNorm1 (gathered) -> bf16, vectorized ----------------
__global__ __launch_bounds__(256) void ln_kernel(const float* __restrict__ x,
                                                 const float* __restrict__ s,
                                                 const float* __restrict__ b,
                                                 __nv_bfloat16* __restrict__ out) {
    int warp = threadIdx.x >> 5;
    int lane = threadIdx.x & 31;
    int row  = blockIdx.x * 8 + warp;
    int src  = win_row_to_tok(row);
    const float2* xp = (const float2*)(x + (size_t)src * C);
    const float2* sp = (const float2*)s;
    const float2* bp = (const float2*)b;

    float2 v[3];
    float sum = 0.f, sq = 0.f;
#pragma unroll
    for (int i = 0; i < 3; i++) {
        v[i] = xp[lane + i * 32];
        sum += v[i].x + v[i].y;
        sq  += v[i].x * v[i].x + v[i].y * v[i].y;
    }
#pragma unroll
    for (int o = 16; o > 0; o >>= 1) {
        sum += __shfl_xor_sync(0xffffffffu, sum, o);
        sq  += __shfl_xor_sync(0xffffffffu, sq, o);
    }
    float mean = sum * (1.f / C);
    float var  = sq * (1.f / C) - mean * mean;
    float rstd = rsqrtf(var + 1e-5f);

    uint32_t* op = (uint32_t*)(out + (size_t)row * C);
#pragma unroll
    for (int i = 0; i < 3; i++) {
        int c2 = lane + i * 32;
        float2 sv = sp[c2], bv = bp[c2];
        op[c2] = packbf((v[i].x - mean) * rstd * sv.x + bv.x,
                        (v[i].y - mean) * rstd * sv.y + bv.y);
    }
}

// ---------------- bf16 MMA GEMM for QKV: R9 proven (256x64, 3-stage) -------
#define GBM 256
#define GBN 64
#define GBK 32
#define QKV_SMEM (3 * (GBM * GBK + GBK * GBN) * 2)   // 61440

__global__ __launch_bounds__(256, 2) void qkv_gemm(const __nv_bfloat16* __restrict__ A,
                                                   const __nv_bfloat16* __restrict__ Bm,
                                                   const float* __restrict__ bias,
                                                   __nv_bfloat16* __restrict__ out,
                                                   int M, int N, int K) {
    extern __shared__ char qsm[];
    uint32_t sa = smem_u32(qsm);
    uint32_t sb = sa + 3 * GBM * GBK * 2;

    int tid  = threadIdx.x;
    int wid  = tid >> 5, lane = tid & 31;
    int wm   = (wid & 3) * 64;
    int wn   = (wid >> 2) * 32;
    int m0   = blockIdx.y * GBM;
    int n0   = blockIdx.x * GBN;

    uint32_t aoff[4][2], boff[2][2];
#pragma unroll
    for (int ma = 0; ma < 4; ma++)
#pragma unroll
        for (int ks = 0; ks < 2; ks++) {
            int row = wm + ma * 16 + (lane & 7) + 8 * ((lane >> 3) & 1);
            int ch  = 2 * ks + (lane >> 4);
            aoff[ma][ks] = row * 64 + ((ch ^ ((row >> 1) & 3)) << 4);
        }
#pragma unroll
    for (int np = 0; np < 2; np++)
#pragma unroll
        for (int ks = 0; ks < 2; ks++) {
            int k  = ks * 16 + (lane & 7) + 8 * ((lane >> 3) & 1);
            int cn = (wn >> 3) + np * 2 + (lane >> 4);
            boff[np][ks] = k * 128 + ((cn ^ (k & 7)) << 4);
        }

    float acc[4][4][4];
#pragma unroll
    for (int i = 0; i < 4; i++)
#pragma unroll
        for (int j = 0; j < 4; j++)
#pragma unroll
            for (int q = 0; q < 4; q++) acc[i][j][q] = 0.f;

    const int nk = K / GBK;
    int arow = tid >> 2, ac = tid & 3;
    int bk = tid >> 3,  bcn = tid & 7;
    uint32_t adst0 = arow * 64 + ((ac ^ ((arow >> 1) & 3)) << 4);
    uint32_t bdst  = bk * 128 + ((bcn ^ (bk & 7)) << 4);

    auto issue = [&](int kt, int buf) {
        const __nv_bfloat16* ga = A + (size_t)m0 * K + kt * GBK + ac * 8;
#pragma unroll
        for (int p = 0; p < 4; p++) {
            int row = arow + p * 64;
            cpasync16(sa + buf * (GBM * GBK * 2) + adst0 + p * 4096,
                      ga + (size_t)row * K);
        }
        cpasync16(sb + buf * (GBK * GBN * 2) + bdst,
                  Bm + (size_t)(kt * GBK + bk) * N + n0 + bcn * 8);
        asm volatile("cp.async.commit_group;" ::: "memory");
    };

    issue(0, 0);
    issue(1, 1);
    for (int kt = 0; kt < nk; kt++) {
        if (kt < nk - 1) {
            asm volatile("cp.async.wait_group 1;" ::: "memory");
        } else {
            asm volatile("cp.async.wait_group 0;" ::: "memory");
        }
        __syncthreads();

        int buf = kt % 3;
        uint32_t ab = sa + buf * (GBM * GBK * 2);
        uint32_t bb = sb + buf * (GBK * GBN * 2);
#pragma unroll
        for (int ks = 0; ks < 2; ks++) {
            uint32_t af[4][4], bfr[4][2];
#pragma unroll
            for (int ma = 0; ma < 4; ma++) ldsm_x4(af[ma], ab + aoff[ma][ks]);
#pragma unroll
            for (int np = 0; np < 2; np++) {
                uint32_t t4[4];
                ldsm_x4_t(t4, bb + boff[np][ks]);
                bfr[np * 2][0] = t4[0]; bfr[np * 2][1] = t4[1];
                bfr[np * 2 + 1][0] = t4[2]; bfr[np * 2 + 1][1] = t4[3];
            }
#pragma unroll
            for (int ma = 0; ma < 4; ma++)
#pragma unroll
                for (int nb = 0; nb < 4; nb++)
                    mma_bf16(acc[ma][nb], af[ma], bfr[nb]);
        }
        if (kt + 2 < nk) issue(kt + 2, (kt + 2) % 3);
    }

    int g = lane >> 2, tig = lane & 3;
#pragma unroll
    for (int ma = 0; ma < 4; ma++) {
        int rlo = m0 + wm + ma * 16 + g;
        int rhi = rlo + 8;
#pragma unroll
        for (int nb = 0; nb < 4; nb++) {
            int col = n0 + wn + nb * 8 + tig * 2;
            float bi0 = bias[col], bi1 = bias[col + 1];
            *(uint32_t*)&out[(size_t)rlo * N + col] = packbf(acc[ma][nb][0] + bi0, acc[ma][nb][1] + bi1);
            *(uint32_t*)&out[(size_t)rhi * N + col] = packbf(acc[ma][nb][2] + bi0, acc[ma][nb][3] + bi1);
        }
    }
}

// ---------------- attention + proj + residual -> x1 (R10, frozen) ----------
#define MK_SMEM 221184

__global__ __launch_bounds__(512) void attnproj_kernel(const __nv_bfloat16* __restrict__ qkv,
                                                       const float* __restrict__ abias,
                                                       const __nv_bfloat16* __restrict__ wproj,
                                                       const float* __restrict__ pbias,
                                                       const float* __restrict__ x,
                                                       float* __restrict__ x1) {
    extern __shared__ char sm[];
    uint32_t sq  = smem_u32(sm);
    uint32_t skb = sq + 49152;
    uint32_t svb = sq + 98304;
    uint32_t sab = sq + 147456;
    uint32_t swb = sq + 196608;
    char* sA_p = sm + 147456;

    int tid  = threadIdx.x;
    int wid  = tid >> 5, lane = tid & 31;
    int m0   = blockIdx.x * 128;
    int g = lane >> 2, q2 = (lane & 3) * 2;

    auto issueW = [&](int s, int buf) {
#pragma unroll
        for (int j = 0; j < 2; j++) {
            int i = tid + j * 512;
            if (i < 768) {
                int kl = i / 24, ch = i % 24;
                cpasync16(swb + buf * 12288 + kl * 384 + ((ch ^ (kl & 7)) << 4),
                          wproj + (size_t)(s * 32 + kl) * 192 + ch * 8);
            }
        }
        asm volatile("cp.async.commit_group;" ::: "memory");
    };

#pragma unroll
    for (int j = 0; j < 18; j++) {
        int i = tid + j * 512;
        int t = i / 72, cc = i % 72;
        int mat = cc / 24, ch = cc % 24;
        int win = t >> 6, r = t & 63;
        cpasync16(sq + mat * 49152 + win * 24576 + r * 384 + ((ch ^ (r & 7)) << 4),
                  qkv + (size_t)(m0 + t) * 576 + cc * 8);
    }
    asm volatile("cp.async.commit_group;" ::: "memory");
    issueW(0, 0);
    asm volatile("cp.async.wait_group 1;" ::: "memory");
    __syncthreads();

#pragma unroll
    for (int it = 0; it < 3; it++) {
        int tk  = wid + it * 16;
        int win = tk / 24;
        int rem = tk - win * 24;
        int hh  = rem >> 2;
        int r4  = rem & 3;
        int r0  = r4 * 16;

        uint32_t qbase = sq  + win * 24576;
        uint32_t kbase = skb + win * 24576;
        uint32_t vbase = svb + win * 24576;

        float sacc[8][4];
#pragma unroll
        for (int i = 0; i < 8; i++)
#pragma unroll
            for (int q = 0; q < 4; q++) sacc[i][q] = 0.f;

        uint32_t qa[2][4];
#pragma unroll
        for (int ks = 0; ks < 2; ks++) {
            int row = r0 + (lane & 7) + 8 * ((lane >> 3) & 1);
            int ch  = hh * 4 + 2 * ks + (lane >> 4);
            ldsm_x4(qa[ks], qbase + row * 384 + ((ch ^ (row & 7)) << 4));
        }
#pragma unroll
        for (int ks = 0; ks < 2; ks++) {
#pragma unroll
            for (int np = 0; np < 4; np++) {
                int tok = np * 16 + (lane & 7) + 8 * (lane >> 4);
                int ch  = hh * 4 + 2 * ks + ((lane >> 3) & 1);
                uint32_t kb[4];
                ldsm_x4(kb, kbase + tok * 384 + ((ch ^ (tok & 7)) << 4));
                mma_bf16(sacc[2 * np],     qa[ks], kb);
                mma_bf16(sacc[2 * np + 1], qa[ks], kb + 2);
            }
        }

        const float scale = 0.17677669529663687f;
        int row0 = r0 + g;
        const float* bt = abias + ((size_t)hh * 64) * 64;
        float mx0 = -1e30f, mx1 = -1e30f;
#pragma unroll
        for (int nb = 0; nb < 8; nb++) {
            int mcol = nb * 8 + q2;
            const float* b0 = bt + row0 * 64 + mcol;
            const float* b1 = b0 + 8 * 64;
            sacc[nb][0] = fmaf(sacc[nb][0], scale, b0[0]);
            sacc[nb][1] = fmaf(sacc[nb][1], scale, b0[1]);
            sacc[nb][2] = fmaf(sacc[nb][2], scale, b1[0]);
            sacc[nb][3] = fmaf(sacc[nb][3], scale, b1[1]);
            mx0 = fmaxf(mx0, fmaxf(sacc[nb][0], sacc[nb][1]));
            mx1 = fmaxf(mx1, fmaxf(sacc[nb][2], sacc[nb][3]));
        }
#pragma unroll
        for (int o = 1; o < 4; o <<= 1) {
            mx0 = fmaxf(mx0, __shfl_xor_sync(0xffffffffu, mx0, o));
            mx1 = fmaxf(mx1, __shfl_xor_sync(0xffffffffu, mx1, o));
        }
        float sum0 = 0.f, sum1 = 0.f;
#pragma unroll
        for (int nb = 0; nb < 8; nb++) {
            sacc[nb][0] = fast_exp(sacc[nb][0] - mx0);
            sacc[nb][1] = fast_exp(sacc[nb][1] - mx0);
            sacc[nb][2] = fast_exp(sacc[nb][2] - mx1);
            sacc[nb][3] = fast_exp(sacc[nb][3] - mx1);
            sum0 += sacc[nb][0] + sacc[nb][1];
            sum1 += sacc[nb][2] + sacc[nb][3];
        }
#pragma unroll
        for (int o = 1; o < 4; o <<= 1) {
            sum0 += __shfl_xor_sync(0xffffffffu, sum0, o);
            sum1 += __shfl_xor_sync(0xffffffffu, sum1, o);
        }

        uint32_t pa[4][4];
#pragma unroll
        for (int ks = 0; ks < 4; ks++) {
            pa[ks][0] = packbf(sacc[2 * ks][0],     sacc[2 * ks][1]);
            pa[ks][1] = packbf(sacc[2 * ks][2],     sacc[2 * ks][3]);
            pa[ks][2] = packbf(sacc[2 * ks + 1][0], sacc[2 * ks + 1][1]);
            pa[ks][3] = packbf(sacc[2 * ks + 1][2], sacc[2 * ks + 1][3]);
        }

        float oacc[4][4];
#pragma unroll
        for (int i = 0; i < 4; i++)
#pragma unroll
            for (int q = 0; q < 4; q++) oacc[i][q] = 0.f;
#pragma unroll
        for (int ks = 0; ks < 4; ks++) {
#pragma unroll
            for (int np = 0; np < 2; np++) {
                int kr = ks * 16 + (lane & 7) + 8 * ((lane >> 3) & 1);
                int cn = hh * 4 + np * 2 + (lane >> 4);
                uint32_t vb[4];
                ldsm_x4_t(vb, vbase + kr * 384 + ((cn ^ (kr & 7)) << 4));
                mma_bf16(oacc[2 * np],     pa[ks], vb);
                mma_bf16(oacc[2 * np + 1], pa[ks], vb + 2);
            }
        }

        float inv0 = 1.f / sum0, inv1 = 1.f / sum1;
        int rl = win * 64 + row0;
        int rh = rl + 8;
#pragma unroll
        for (int nb = 0; nb < 4; nb++) {
            int chA = hh * 4 + nb;
            *(uint32_t*)(sA_p + rl * 384 + ((chA ^ (rl & 7)) << 4) + q2 * 2) =
                packbf(oacc[nb][0] * inv0, oacc[nb][1] * inv0);
            *(uint32_t*)(sA_p + rh * 384 + ((chA ^ (rh & 7)) << 4) + q2 * 2) =
                packbf(oacc[nb][2] * inv1, oacc[nb][3] * inv1);
        }
    }
    __syncthreads();

    int wm = (wid & 3) * 32;
    int wn = (wid >> 2) * 48;
    float acc[2][6][4];
#pragma unroll
    for (int i = 0; i < 2; i++)
#pragma unroll
        for (int j = 0; j < 6; j++)
#pragma unroll
            for (int q = 0; q < 4; q++) acc[i][j][q] = 0.f;

    for (int s = 0; s < 6; s++) {
        if (s < 5) {
            issueW(s + 1, (s + 1) & 1);
            asm volatile("cp.async.wait_group 1;" ::: "memory");
        } else {
            asm volatile("cp.async.wait_group 0;" ::: "memory");
        }
        __syncthreads();
        uint32_t bb = swb + (s & 1) * 12288;
#pragma unroll
        for (int t = 0; t < 2; t++) {
            uint32_t af[2][4];
#pragma unroll
            for (int fi = 0; fi < 2; fi++) {
                int row = wm + fi * 16 + (lane & 7) + 8 * ((lane >> 3) & 1);
                int ch  = 4 * s + 2 * t + (lane >> 4);
                ldsm_x4(af[fi], sab + row * 384 + ((ch ^ (row & 7)) << 4));
            }
            uint32_t bfr[6][2];
#pragma unroll
            for (int j = 0; j < 3; j++) {
                int kl = t * 16 + (lane & 7) + 8 * ((lane >> 3) & 1);
                int cn = (wn >> 3) + 2 * j + (lane >> 4);
                uint32_t t4[4];
                ldsm_x4_t(t4, bb + kl * 384 + ((cn ^ (kl & 7)) << 4));
                bfr[2 * j][0] = t4[0]; bfr[2 * j][1] = t4[1];
                bfr[2 * j + 1][0] = t4[2]; bfr[2 * j + 1][1] = t4[3];
            }
#pragma unroll
            for (int fi = 0; fi < 2; fi++)
#pragma unroll
                for (int nj = 0; nj < 6; nj++)
                    mma_bf16(acc[fi][nj], af[fi], bfr[nj]);
        }
        __syncthreads();
    }

#pragma unroll
    for (int fi = 0; fi < 2; fi++) {
        int rl = wm + fi * 16 + g;
        int rh = rl + 8;
        int tokl = win_row_to_tok(m0 + rl);
        int tokh = win_row_to_tok(m0 + rh);
#pragma unroll
        for (int nj = 0; nj < 6; nj++) {
            int col = wn + nj * 8 + q2;
            float bi0 = pbias[col], bi1 = pbias[col + 1];
            float2 xl = *(const float2*)&x[(size_t)tokl * C + col];
            float2 xh = *(const float2*)&x[(size_t)tokh * C + col];
            *(float2*)&x1[(size_t)tokl * C + col] =
                make_float2(acc[fi][nj][0] + bi0 + xl.x, acc[fi][nj][1] + bi1 + xl.y);
            *(float2*)&x1[(size_t)tokh * C + col] =
                make_float2(acc[fi][nj][2] + bi0 + xh.x, acc[fi][nj][3] + bi1 + xh.y);
        }
    }
}

// ---------------- fused MLP + LN2 (R10, frozen) ----------------------------
#define MLP_SMEM 223232
#define X1W 196

__device__ __forceinline__ void mlp_gemm_inner(uint32_t aBase, uint32_t sbBase,
                                               const __nv_bfloat16* __restrict__ Wg,
                                               int rstride, int rowbase, int coloff,
                                               int wm, int wn, int tid, int lane,
                                               float acc[2][6][4]) {
    auto issueW = [&](int s, int buf) {
#pragma unroll
        for (int j = 0; j < 2; j++) {
            int i = tid + j * 512;
            if (i < 768) {
                int kl = i / 24, cch = i % 24;
                cpasync16(sbBase + buf * 12288 + kl * 384 + ((cch ^ (kl & 7)) << 4),
                          Wg + (size_t)(rowbase + s * 32 + kl) * rstride + coloff + cch * 8);
            }
        }
        asm volatile("cp.async.commit_group;" ::: "memory");
    };

    issueW(0, 0);
    for (int s = 0; s < 6; s++) {
        if (s < 5) {
            issueW(s + 1, (s + 1) & 1);
            asm volatile("cp.async.wait_group 1;" ::: "memory");
        } else {
            asm volatile("cp.async.wait_group 0;" ::: "memory");
        }
        __syncthreads();
        uint32_t bb = sbBase + (s & 1) * 12288;
#pragma unroll
        for (int t = 0; t < 2; t++) {
            int kk = s * 2 + t;
            uint32_t af[2][4];
#pragma unroll
            for (int fi = 0; fi < 2; fi++) {
                int row = wm + fi * 16 + (lane & 7) + 8 * ((lane >> 3) & 1);
                int ch  = 2 * kk + (lane >> 4);
                ldsm_x4(af[fi], aBase + row * 384 + ((ch ^ (row & 7)) << 4));
            }
            uint32_t bfr[6][2];
#pragma unroll
            for (int j = 0; j < 3; j++) {
                int kl = t * 16 + (lane & 7) + 8 * ((lane >> 3) & 1);
                int cn = (wn >> 3) + 2 * j + (lane >> 4);
                uint32_t t4[4];
                ldsm_x4_t(t4, bb + kl * 384 + ((cn ^ (kl & 7)) << 4));
                bfr[2 * j][0] = t4[0]; bfr[2 * j][1] = t4[1];
                bfr[2 * j + 1][0] = t4[2]; bfr[2 * j + 1][1] = t4[3];
            }
#pragma unroll
            for (int fi = 0; fi < 2; fi++)
#pragma unroll
                for (int nj = 0; nj < 6; nj++)
                    mma_bf16(acc[fi][nj], af[fi], bfr[nj]);
        }
        __syncthreads();
    }
}

__global__ __launch_bounds__(512) void mlp_kernel(const float* __restrict__ x1,
                                                  const float* __restrict__ n2s,
                                                  const float* __restrict__ n2b,
                                                  const __nv_bfloat16* __restrict__ w1,
                                                  const float* __restrict__ b1,
                                                  const __nv_bfloat16* __restrict__ w2,
                                                  const float* __restrict__ b2,
                                                  float* __restrict__ out) {
    extern __shared__ char sm[];
    float* sX1 = (float*)sm;
    char* sXn_p = sm + 100352;
    char* sH_p  = sm + 149504;
    uint32_t sx1b = smem_u32(sm);
    uint32_t sxn  = sx1b + 100352;
    uint32_t shb  = sx1b + 149504;
    uint32_t sbb  = sx1b + 198656;

    int tid = threadIdx.x;
    int wid = tid >> 5, lane = tid & 31;
    int m0 = blockIdx.x * 128;
    int wm = (wid & 3) * 32;
    int wn = (wid >> 2) * 48;
    int g = lane >> 2, q2 = (lane & 3) * 2;

#pragma unroll
    for (int j = 0; j < 12; j++) {
        int i = tid + j * 512;
        int r = i / 48, cc = i % 48;
        cpasync16(sx1b + r * (X1W * 4) + cc * 16, x1 + (size_t)(m0 + r) * C + cc * 4);
    }
    asm volatile("cp.async.commit_group;" ::: "memory");
    asm volatile("cp.async.wait_group 0;" ::: "memory");
    __syncthreads();

    {
        const float2* sp = (const float2*)n2s;
        const float2* bp = (const float2*)n2b;
        float2 sg[3], bg[3];
#pragma unroll
        for (int i = 0; i < 3; i++) {
            sg[i] = sp[lane + i * 32];
            bg[i] = bp[lane + i * 32];
        }
#pragma unroll
        for (int rr = 0; rr < 8; rr++) {
            int row = wid * 8 + rr;
            const float2* rp = (const float2*)(sX1 + row * X1W);
            float2 v[3];
            float sum = 0.f, sq = 0.f;
#pragma unroll
            for (int i = 0; i < 3; i++) {
                v[i] = rp[lane + i * 32];
                sum += v[i].x + v[i].y;
                sq  += v[i].x * v[i].x + v[i].y * v[i].y;
            }
#pragma unroll
            for (int o = 16; o > 0; o >>= 1) {
                sum += __shfl_xor_sync(0xffffffffu, sum, o);
                sq  += __shfl_xor_sync(0xffffffffu, sq, o);
            }
            float mean = sum * (1.f / C);
            float var  = sq * (1.f / C) - mean * mean;
            float rstd = rsqrtf(var + 1e-5f);
#pragma unroll
            for (int i = 0; i < 3; i++) {
                int c2 = lane + i * 32;
                uint32_t val = packbf((v[i].x - mean) * rstd * sg[i].x + bg[i].x,
                                      (v[i].y - mean) * rstd * sg[i].y + bg[i].y);
                int ch = c2 >> 2;
                *(uint32_t*)(sXn_p + row * 384 + ((ch ^ (row & 7)) << 4) + (c2 & 3) * 4) = val;
            }
        }
    }
    __syncthreads();

    float acc2[2][6][4];
#pragma unroll
    for (int i = 0; i < 2; i++)
#pragma unroll
        for (int j = 0; j < 6; j++)
#pragma unroll
            for (int q = 0; q < 4; q++) acc2[i][j][q] = 0.f;

    for (int c = 0; c < 4; c++) {
        float acc1[2][6][4];
#pragma unroll
        for (int i = 0; i < 2; i++)
#pragma unroll
            for (int j = 0; j < 6; j++)
#pragma unroll
                for (int q = 0; q < 4; q++) acc1[i][j][q] = 0.f;
        mlp_gemm_inner(sxn, sbb, w1, 4 * C, 0, c * 192, wm, wn, tid, lane, acc1);

        const float is2 = 0.70710678118654752f;
#pragma unroll
        for (int fi = 0; fi < 2; fi++) {
            int rl = wm + fi * 16 + g;
            int rh = rl + 8;
#pragma unroll
            for (int nj = 0; nj < 6; nj++) {
                int colL = wn + nj * 8 + q2;
                int gcol = c * 192 + colL;
                float bi0 = b1[gcol], bi1 = b1[gcol + 1];
                float v00 = acc1[fi][nj][0] + bi0;
                float v01 = acc1[fi][nj][1] + bi1;
                float v10 = acc1[fi][nj][2] + bi0;
                float v11 = acc1[fi][nj][3] + bi1;
                v00 = 0.5f * v00 * (1.f + erff(v00 * is2));
                v01 = 0.5f * v01 * (1.f + erff(v01 * is2));
                v10 = 0.5f * v10 * (1.f + erff(v10 * is2));
                v11 = 0.5f * v11 * (1.f + erff(v11 * is2));
                int chh = colL >> 3;
                *(uint32_t*)(sH_p + rl * 384 + ((chh ^ (rl & 7)) << 4) + q2 * 2) = packbf(v00, v01);
                *(uint32_t*)(sH_p + rh * 384 + ((chh ^ (rh & 7)) << 4) + q2 * 2) = packbf(v10, v11);
            }
        }
        __syncthreads();

        mlp_gemm_inner(shb, sbb, w2, C, c * 192, 0, wm, wn, tid, lane, acc2);
    }

#pragma unroll
    for (int fi = 0; fi < 2; fi++) {
        int rl = wm + fi * 16 + g;
        int rh = rl + 8;
        int ml = m0 + rl, mh = m0 + rh;
#pragma unroll
        for (int nj = 0; nj < 6; nj++) {
            int col = wn + nj * 8 + q2;
            float bi0 = b2[col], bi1 = b2[col + 1];
            float xl0 = sX1[rl * X1W + col],     xl1 = sX1[rl * X1W + col + 1];
            float xh0 = sX1[rh * X1W + col],     xh1 = sX1[rh * X1W + col + 1];
            *(float2*)&out[(size_t)ml * C + col] =
                make_float2(acc2[fi][nj][0] + bi0 + xl0, acc2[fi][nj][1] + bi1 + xl1);
            *(float2*)&out[(size_t)mh * C + col] =
                make_float2(acc2[fi][nj][2] + bi0 + xh0, acc2[fi][nj][3] + bi1 + xh1);
        }
    }
}

// ---------------- launch ---------------------------------------------------
extern "C" void kernel_launch(void* const* d_in, const int* in_sizes, int n_in,
                              void* d_out, int out_size) {
    const float* x      = (const float*)d_in[0];
    const float* qkv_w  = (const float*)d_in[1];
    const float* qkv_b  = (const float*)d_in[2];
    const float* proj_w = (const float*)d_in[3];
    const float* proj_b = (const float*)d_in[4];
    const float* rpb    = (const float*)d_in[5];
    const float* n1s    = (const float*)d_in[6];
    const float* n1b    = (const float*)d_in[7];
    const float* n2s    = (const float*)d_in[8];
    const float* n2b    = (const float*)d_in[9];
    const float* w1     = (const float*)d_in[10];
    const float* b1     = (const float*)d_in[11];
    const float* w2     = (const float*)d_in[12];
    const float* b2     = (const float*)d_in[13];
    float* out = (float*)d_out;

    __nv_bfloat16 *xw, *qkv, *wqkv, *wproj, *ww1, *ww2;
    float *x1, *abias;
    cudaGetSymbolAddress((void**)&xw,    g_xw);
    cudaGetSymbolAddress((void**)&qkv,   g_qkv);
    cudaGetSymbolAddress((void**)&x1,    g_x1);
    cudaGetSymbolAddress((void**)&wqkv,  g_wqkv);
    cudaGetSymbolAddress((void**)&wproj, g_wproj);
    cudaGetSymbolAddress((void**)&ww1,   g_w1);
    cudaGetSymbolAddress((void**)&ww2,   g_w2);
    cudaGetSymbolAddress((void**)&abias, g_abias);

    cudaFuncSetAttribute(qkv_gemm,        cudaFuncAttributeMaxDynamicSharedMemorySize, QKV_SMEM);
    cudaFuncSetAttribute(attnproj_kernel, cudaFuncAttributeMaxDynamicSharedMemorySize, MK_SMEM);
    cudaFuncSetAttribute(mlp_kernel,      cudaFuncAttributeMaxDynamicSharedMemorySize, MLP_SMEM);

    // prep (single launch: weights + abias)
    prep_kernel<<<(SZ_ALL + 255) / 256, 256>>>(qkv_w, proj_w, w1, w2, rpb,
                                               wqkv, wproj, ww1, ww2, abias);

    // 1. LN1 + shift + window gather -> bf16
    ln_kernel<<<NTOK / 8, 256>>>(x, n1s, n1b, xw);

    // 2. QKV GEMM -> bf16
    qkv_gemm<<<dim3((3 * C) / GBN, NTOK / GBM), 256, QKV_SMEM>>>(xw, wqkv, qkv_b, qkv,
                                                                 NTOK, 3 * C, C);

    // 3. attention + proj + residual -> x1 (fp32, token order)
    attnproj_kernel<<<NTOK / 128, 512, MK_SMEM>>>(qkv, abias, wproj, proj_b, x, x1);

    // 4. fused LN2 + MLP + residual -> out
    mlp_kernel<<<NTOK / 128, 512, MLP_SMEM>>>(x1, n2s, n2b, ww1, b1, ww2, b2, out);
}

// round 14
// speedup vs baseline: 1.1636x; 1.0127x over previous
#include <cuda_runtime.h>
#include <cuda_bf16.h>
#include <math.h>
#include <stdint.h>

// Problem constants
#define BATCH   8
#define HW      128
#define LTOK    16384
#define C       192
#define WS      8
#define SHIFT   4
#define NH      6
#define HD      32
#define NWIN    2048
#define NTOK    131072

// ---------------- scratch (device globals) ---------------------------------
__device__ __nv_bfloat16 g_xw  [(size_t)NTOK * C];
__device__ __nv_bfloat16 g_qkv [(size_t)NTOK * 3 * C];
__device__ float         g_x1  [(size_t)NTOK * C];
__device__ __nv_bfloat16 g_wqkv [C * 3 * C];    // [K,N] bf16
__device__ __nv_bfloat16 g_wproj[C * C];        // [K,N] bf16
__device__ __nv_bfloat16 g_w1   [C * 4 * C];    // [K,N] bf16
__device__ __nv_bfloat16 g_w2   [4 * C * C];    // [K,N] bf16
__device__ float         g_abias[NH * 64 * 64];

// ---------------- helpers --------------------------------------------------
__device__ __forceinline__ uint32_t smem_u32(const void* p) {
    return (uint32_t)__cvta_generic_to_shared(p);
}
__device__ __forceinline__ void cpasync16(uint32_t dst, const void* src) {
    asm volatile("cp.async.cg.shared.global [%0], [%1], 16;" :: "r"(dst), "l"(src));
}
__device__ __forceinline__ void ldsm_x4(uint32_t* r, uint32_t addr) {
    asm volatile("ldmatrix.sync.aligned.m8n8.x4.shared.b16 {%0,%1,%2,%3}, [%4];"
        : "=r"(r[0]), "=r"(r[1]), "=r"(r[2]), "=r"(r[3]) : "r"(addr));
}
__device__ __forceinline__ void ldsm_x4_t(uint32_t* r, uint32_t addr) {
    asm volatile("ldmatrix.sync.aligned.m8n8.x4.trans.shared.b16 {%0,%1,%2,%3}, [%4];"
        : "=r"(r[0]), "=r"(r[1]), "=r"(r[2]), "=r"(r[3]) : "r"(addr));
}
__device__ __forceinline__ void mma_bf16(float* d, const uint32_t* a, const uint32_t* b) {
    asm volatile(
        "mma.sync.aligned.m16n8k16.row.col.f32.bf16.bf16.f32 "
        "{%0,%1,%2,%3}, {%4,%5,%6,%7}, {%8,%9}, {%0,%1,%2,%3};"
        : "+f"(d[0]), "+f"(d[1]), "+f"(d[2]), "+f"(d[3])
        : "r"(a[0]), "r"(a[1]), "r"(a[2]), "r"(a[3]), "r"(b[0]), "r"(b[1]));
}
__device__ __forceinline__ uint32_t packbf(float lo, float hi) {
    uint32_t r;
    asm("cvt.rn.bf16x2.f32 %0, %1, %2;" : "=r"(r) : "f"(hi), "f"(lo));
    return r;
}
__device__ __forceinline__ float fast_exp(float x) {
    float t = fminf(fmaxf(x * 1.4426950408889634f, -100.f), 80.f);
    float z = t + 12582912.f;
    int   ni = __float_as_int(z);
    float nf = z - 12582912.f;
    float f  = t - nf;
    float p = 1.33335581e-3f;
    p = fmaf(p, f, 9.61812910e-3f);
    p = fmaf(p, f, 5.55041087e-2f);
    p = fmaf(p, f, 2.40226507e-1f);
    p = fmaf(p, f, 6.93147181e-1f);
    p = fmaf(p, f, 1.0f);
    float sc = __int_as_float((((ni & 0x7FFFFF) - 0x400000) + 127) << 23);
    return p * sc;
}

// window-row (w*64+n) -> flat token index
__device__ __forceinline__ int win_row_to_tok(int row) {
    int w  = row >> 6;
    int n  = row & 63;
    int b  = w >> 8;
    int wy = (w >> 4) & 15;
    int wx = w & 15;
    int iy = n >> 3;
    int ix = n & 7;
    int hr = (wy * WS + iy + SHIFT) & (HW - 1);
    int wr = (wx * WS + ix + SHIFT) & (HW - 1);
    return (b << 14) + (hr << 7) + wr;
}

// ---------------- merged prologue: LN1 blocks + prep blocks ------------------
#define SZ_QKVW (C * 3 * C)
#define SZ_PROJ (C * C)
#define SZ_W1   (C * 4 * C)
#define SZ_W2   (4 * C * C)
#define SZ_WALL (SZ_QKVW + SZ_PROJ + SZ_W1 + SZ_W2)
#define SZ_AB   (NH * 64 * 64)
#define SZ_PALL (SZ_WALL + SZ_AB)
#define LN_BLOCKS   (NTOK / 8)
#define PREP_BLOCKS ((SZ_PALL + 255) / 256)

__global__ __launch_bounds__(256) void prologue_kernel(const float* __restrict__ x,
                                                       const float* __restrict__ n1s,
                                                       const float* __restrict__ n1b,
                                                       const float* __restrict__ qkv_w,
                                                       const float* __restrict__ proj_w,
                                                       const float* __restrict__ w1,
                                                       const float* __restrict__ w2,
                                                       const float* __restrict__ rpb,
                                                       __nv_bfloat16* __restrict__ xw,
                                                       __nv_bfloat16* __restrict__ wqkv,
                                                       __nv_bfloat16* __restrict__ wproj,
                                                       __nv_bfloat16* __restrict__ ow1,
                                                       __nv_bfloat16* __restrict__ ow2,
                                                       float* __restrict__ abias) {
    if (blockIdx.x < LN_BLOCKS) {
        // -------- LN1 + shift + window gather -> bf16 (one warp per token) --
        int warp = threadIdx.x >> 5;
        int lane = threadIdx.x & 31;
        int row  = blockIdx.x * 8 + warp;
        int src  = win_row_to_tok(row);
        const float2* xp = (const float2*)(x + (size_t)src * C);
        const float2* sp = (const float2*)n1s;
        const float2* bp = (const float2*)n1b;

        float2 v[3];
        float sum = 0.f, sq = 0.f;
#pragma unroll
        for (int i = 0; i < 3; i++) {
            v[i] = xp[lane + i * 32];
            sum += v[i].x + v[i].y;
            sq  += v[i].x * v[i].x + v[i].y * v[i].y;
        }
#pragma unroll
        for (int o = 16; o > 0; o >>= 1) {
            sum += __shfl_xor_sync(0xffffffffu, sum, o);
            sq  += __shfl_xor_sync(0xffffffffu, sq, o);
        }
        float mean = sum * (1.f / C);
        float var  = sq * (1.f / C) - mean * mean;
        float rstd = rsqrtf(var + 1e-5f);

        uint32_t* op = (uint32_t*)(xw + (size_t)row * C);
#pragma unroll
        for (int i = 0; i < 3; i++) {
            int c2 = lane + i * 32;
            float2 sv = sp[c2], bv = bp[c2];
            op[c2] = packbf((v[i].x - mean) * rstd * sv.x + bv.x,
                            (v[i].y - mean) * rstd * sv.y + bv.y);
        }
    } else {
        // -------- weight conversion + abias expansion ----------------------
        int i = (blockIdx.x - LN_BLOCKS) * 256 + threadIdx.x;
        if (i >= SZ_PALL) return;
        if (i < SZ_QKVW) {
            wqkv[i] = __float2bfloat16(qkv_w[i]);
        } else if (i < SZ_QKVW + SZ_PROJ) {
            int j = i - SZ_QKVW;
            wproj[j] = __float2bfloat16(proj_w[j]);
        } else if (i < SZ_QKVW + SZ_PROJ + SZ_W1) {
            int j = i - SZ_QKVW - SZ_PROJ;
            ow1[j] = __float2bfloat16(w1[j]);
        } else if (i < SZ_WALL) {
            int j = i - SZ_QKVW - SZ_PROJ - SZ_W1;
            ow2[j] = __float2bfloat16(w2[j]);
        } else {
            int j = i - SZ_WALL;
            int h = j >> 12;
            int n = (j >> 6) & 63;
            int m = j & 63;
            int iy = n >> 3, ix = n & 7, jy = m >> 3, jx = m & 7;
            int ridx = (iy - jy + 7) * 15 + (ix - jx + 7);
            abias[j] = rpb[ridx * NH + h];
        }
    }
}

// ---------------- bf16 MMA GEMM for QKV: R9 proven (256x64, 3-stage) -------
#define GBM 256
#define GBN 64
#define GBK 32
#define QKV_SMEM (3 * (GBM * GBK + GBK * GBN) * 2)   // 61440

__global__ __launch_bounds__(256, 2) void qkv_gemm(const __nv_bfloat16* __restrict__ A,
                                                   const __nv_bfloat16* __restrict__ Bm,
                                                   const float* __restrict__ bias,
                                                   __nv_bfloat16* __restrict__ out,
                                                   int M, int N, int K) {
    extern __shared__ char qsm[];
    uint32_t sa = smem_u32(qsm);
    uint32_t sb = sa + 3 * GBM * GBK * 2;

    int tid  = threadIdx.x;
    int wid  = tid >> 5, lane = tid & 31;
    int wm   = (wid & 3) * 64;
    int wn   = (wid >> 2) * 32;
    int m0   = blockIdx.y * GBM;
    int n0   = blockIdx.x * GBN;

    uint32_t aoff[4][2], boff[2][2];
#pragma unroll
    for (int ma = 0; ma < 4; ma++)
#pragma unroll
        for (int ks = 0; ks < 2; ks++) {
            int row = wm + ma * 16 + (lane & 7) + 8 * ((lane >> 3) & 1);
            int ch  = 2 * ks + (lane >> 4);
            aoff[ma][ks] = row * 64 + ((ch ^ ((row >> 1) & 3)) << 4);
        }
#pragma unroll
    for (int np = 0; np < 2; np++)
#pragma unroll
        for (int ks = 0; ks < 2; ks++) {
            int k  = ks * 16 + (lane & 7) + 8 * ((lane >> 3) & 1);
            int cn = (wn >> 3) + np * 2 + (lane >> 4);
            boff[np][ks] = k * 128 + ((cn ^ (k & 7)) << 4);
        }

    float acc[4][4][4];
#pragma unroll
    for (int i = 0; i < 4; i++)
#pragma unroll
        for (int j = 0; j < 4; j++)
#pragma unroll
            for (int q = 0; q < 4; q++) acc[i][j][q] = 0.f;

    const int nk = K / GBK;
    int arow = tid >> 2, ac = tid & 3;
    int bk = tid >> 3,  bcn = tid & 7;
    uint32_t adst0 = arow * 64 + ((ac ^ ((arow >> 1) & 3)) << 4);
    uint32_t bdst  = bk * 128 + ((bcn ^ (bk & 7)) << 4);

    auto issue = [&](int kt, int buf) {
        const __nv_bfloat16* ga = A + (size_t)m0 * K + kt * GBK + ac * 8;
#pragma unroll
        for (int p = 0; p < 4; p++) {
            int row = arow + p * 64;
            cpasync16(sa + buf * (GBM * GBK * 2) + adst0 + p * 4096,
                      ga + (size_t)row * K);
        }
        cpasync16(sb + buf * (GBK * GBN * 2) + bdst,
                  Bm + (size_t)(kt * GBK + bk) * N + n0 + bcn * 8);
        asm volatile("cp.async.commit_group;" ::: "memory");
    };

    issue(0, 0);
    issue(1, 1);
    for (int kt = 0; kt < nk; kt++) {
        if (kt < nk - 1) {
            asm volatile("cp.async.wait_group 1;" ::: "memory");
        } else {
            asm volatile("cp.async.wait_group 0;" ::: "memory");
        }
        __syncthreads();

        int buf = kt % 3;
        uint32_t ab = sa + buf * (GBM * GBK * 2);
        uint32_t bb = sb + buf * (GBK * GBN * 2);
#pragma unroll
        for (int ks = 0; ks < 2; ks++) {
            uint32_t af[4][4], bfr[4][2];
#pragma unroll
            for (int ma = 0; ma < 4; ma++) ldsm_x4(af[ma], ab + aoff[ma][ks]);
#pragma unroll
            for (int np = 0; np < 2; np++) {
                uint32_t t4[4];
                ldsm_x4_t(t4, bb + boff[np][ks]);
                bfr[np * 2][0] = t4[0]; bfr[np * 2][1] = t4[1];
                bfr[np * 2 + 1][0] = t4[2]; bfr[np * 2 + 1][1] = t4[3];
            }
#pragma unroll
            for (int ma = 0; ma < 4; ma++)
#pragma unroll
                for (int nb = 0; nb < 4; nb++)
                    mma_bf16(acc[ma][nb], af[ma], bfr[nb]);
        }
        if (kt + 2 < nk) issue(kt + 2, (kt + 2) % 3);
    }

    int g = lane >> 2, tig = lane & 3;
#pragma unroll
    for (int ma = 0; ma < 4; ma++) {
        int rlo = m0 + wm + ma * 16 + g;
        int rhi = rlo + 8;
#pragma unroll
        for (int nb = 0; nb < 4; nb++) {
            int col = n0 + wn + nb * 8 + tig * 2;
            float bi0 = bias[col], bi1 = bias[col + 1];
            *(uint32_t*)&out[(size_t)rlo * N + col] = packbf(acc[ma][nb][0] + bi0, acc[ma][nb][1] + bi1);
            *(uint32_t*)&out[(size_t)rhi * N + col] = packbf(acc[ma][nb][2] + bi0, acc[ma][nb][3] + bi1);
        }
    }
}

// ---------------- attention + proj + residual -> x1 (no-max softmax) -------
#define MK_SMEM 221184

__global__ __launch_bounds__(512) void attnproj_kernel(const __nv_bfloat16* __restrict__ qkv,
                                                       const float* __restrict__ abias,
                                                       const __nv_bfloat16* __restrict__ wproj,
                                                       const float* __restrict__ pbias,
                                                       const float* __restrict__ x,
                                                       float* __restrict__ x1) {
    extern __shared__ char sm[];
    uint32_t sq  = smem_u32(sm);
    uint32_t skb = sq + 49152;
    uint32_t svb = sq + 98304;
    uint32_t sab = sq + 147456;
    uint32_t swb = sq + 196608;
    char* sA_p = sm + 147456;

    int tid  = threadIdx.x;
    int wid  = tid >> 5, lane = tid & 31;
    int m0   = blockIdx.x * 128;
    int g = lane >> 2, q2 = (lane & 3) * 2;

    auto issueW = [&](int s, int buf) {
#pragma unroll
        for (int j = 0; j < 2; j++) {
            int i = tid + j * 512;
            if (i < 768) {
                int kl = i / 24, ch = i % 24;
                cpasync16(swb + buf * 12288 + kl * 384 + ((ch ^ (kl & 7)) << 4),
                          wproj + (size_t)(s * 32 + kl) * 192 + ch * 8);
            }
        }
        asm volatile("cp.async.commit_group;" ::: "memory");
    };

#pragma unroll
    for (int j = 0; j < 18; j++) {
        int i = tid + j * 512;
        int t = i / 72, cc = i % 72;
        int mat = cc / 24, ch = cc % 24;
        int win = t >> 6, r = t & 63;
        cpasync16(sq + mat * 49152 + win * 24576 + r * 384 + ((ch ^ (r & 7)) << 4),
                  qkv + (size_t)(m0 + t) * 576 + cc * 8);
    }
    asm volatile("cp.async.commit_group;" ::: "memory");
    issueW(0, 0);
    asm volatile("cp.async.wait_group 1;" ::: "memory");
    __syncthreads();

#pragma unroll
    for (int it = 0; it < 3; it++) {
        int tk  = wid + it * 16;
        int win = tk / 24;
        int rem = tk - win * 24;
        int hh  = rem >> 2;
        int r4  = rem & 3;
        int r0  = r4 * 16;

        uint32_t qbase = sq  + win * 24576;
        uint32_t kbase = skb + win * 24576;
        uint32_t vbase = svb + win * 24576;

        float sacc[8][4];
#pragma unroll
        for (int i = 0; i < 8; i++)
#pragma unroll
            for (int q = 0; q < 4; q++) sacc[i][q] = 0.f;

        uint32_t qa[2][4];
#pragma unroll
        for (int ks = 0; ks < 2; ks++) {
            int row = r0 + (lane & 7) + 8 * ((lane >> 3) & 1);
            int ch  = hh * 4 + 2 * ks + (lane >> 4);
            ldsm_x4(qa[ks], qbase + row * 384 + ((ch ^ (row & 7)) << 4));
        }
#pragma unroll
        for (int ks = 0; ks < 2; ks++) {
#pragma unroll
            for (int np = 0; np < 4; np++) {
                int tok = np * 16 + (lane & 7) + 8 * (lane >> 4);
                int ch  = hh * 4 + 2 * ks + ((lane >> 3) & 1);
                uint32_t kb[4];
                ldsm_x4(kb, kbase + tok * 384 + ((ch ^ (tok & 7)) << 4));
                mma_bf16(sacc[2 * np],     qa[ks], kb);
                mma_bf16(sacc[2 * np + 1], qa[ks], kb + 2);
            }
        }

        // bias + softmax WITHOUT max-subtraction (scores are O(1) here;
        // fast_exp clamps at +80/-100 so overflow is impossible)
        const float scale = 0.17677669529663687f;
        int row0 = r0 + g;
        const float* bt = abias + ((size_t)hh * 64) * 64;
        float sum0 = 0.f, sum1 = 0.f;
#pragma unroll
        for (int nb = 0; nb < 8; nb++) {
            int mcol = nb * 8 + q2;
            const float* b0 = bt + row0 * 64 + mcol;
            const float* b1 = b0 + 8 * 64;
            sacc[nb][0] = fast_exp(fmaf(sacc[nb][0], scale, b0[0]));
            sacc[nb][1] = fast_exp(fmaf(sacc[nb][1], scale, b0[1]));
            sacc[nb][2] = fast_exp(fmaf(sacc[nb][2], scale, b1[0]));
            sacc[nb][3] = fast_exp(fmaf(sacc[nb][3], scale, b1[1]));
            sum0 += sacc[nb][0] + sacc[nb][1];
            sum1 += sacc[nb][2] + sacc[nb][3];
        }
#pragma unroll
        for (int o = 1; o < 4; o <<= 1) {
            sum0 += __shfl_xor_sync(0xffffffffu, sum0, o);
            sum1 += __shfl_xor_sync(0xffffffffu, sum1, o);
        }

        uint32_t pa[4][4];
#pragma unroll
        for (int ks = 0; ks < 4; ks++) {
            pa[ks][0] = packbf(sacc[2 * ks][0],     sacc[2 * ks][1]);
            pa[ks][1] = packbf(sacc[2 * ks][2],     sacc[2 * ks][3]);
            pa[ks][2] = packbf(sacc[2 * ks + 1][0], sacc[2 * ks + 1][1]);
            pa[ks][3] = packbf(sacc[2 * ks + 1][2], sacc[2 * ks + 1][3]);
        }

        float oacc[4][4];
#pragma unroll
        for (int i = 0; i < 4; i++)
#pragma unroll
            for (int q = 0; q < 4; q++) oacc[i][q] = 0.f;
#pragma unroll
        for (int ks = 0; ks < 4; ks++) {
#pragma unroll
            for (int np = 0; np < 2; np++) {
                int kr = ks * 16 + (lane & 7) + 8 * ((lane >> 3) & 1);
                int cn = hh * 4 + np * 2 + (lane >> 4);
                uint32_t vb[4];
                ldsm_x4_t(vb, vbase + kr * 384 + ((cn ^ (kr & 7)) << 4));
                mma_bf16(oacc[2 * np],     pa[ks], vb);
                mma_bf16(oacc[2 * np + 1], pa[ks], vb + 2);
            }
        }

        float inv0 = 1.f / sum0, inv1 = 1.f / sum1;
        int rl = win * 64 + row0;
        int rh = rl + 8;
#pragma unroll
        for (int nb = 0; nb < 4; nb++) {
            int chA = hh * 4 + nb;
            *(uint32_t*)(sA_p + rl * 384 + ((chA ^ (rl & 7)) << 4) + q2 * 2) =
                packbf(oacc[nb][0] * inv0, oacc[nb][1] * inv0);
            *(uint32_t*)(sA_p + rh * 384 + ((chA ^ (rh & 7)) << 4) + q2 * 2) =
                packbf(oacc[nb][2] * inv1, oacc[nb][3] * inv1);
        }
    }
    __syncthreads();

    int wm = (wid & 3) * 32;
    int wn = (wid >> 2) * 48;
    float acc[2][6][4];
#pragma unroll
    for (int i = 0; i < 2; i++)
#pragma unroll
        for (int j = 0; j < 6; j++)
#pragma unroll
            for (int q = 0; q < 4; q++) acc[i][j][q] = 0.f;

    for (int s = 0; s < 6; s++) {
        if (s < 5) {
            issueW(s + 1, (s + 1) & 1);
            asm volatile("cp.async.wait_group 1;" ::: "memory");
        } else {
            asm volatile("cp.async.wait_group 0;" ::: "memory");
        }
        __syncthreads();
        uint32_t bb = swb + (s & 1) * 12288;
#pragma unroll
        for (int t = 0; t < 2; t++) {
            uint32_t af[2][4];
#pragma unroll
            for (int fi = 0; fi < 2; fi++) {
                int row = wm + fi * 16 + (lane & 7) + 8 * ((lane >> 3) & 1);
                int ch  = 4 * s + 2 * t + (lane >> 4);
                ldsm_x4(af[fi], sab + row * 384 + ((ch ^ (row & 7)) << 4));
            }
            uint32_t bfr[6][2];
#pragma unroll
            for (int j = 0; j < 3; j++) {
                int kl = t * 16 + (lane & 7) + 8 * ((lane >> 3) & 1);
                int cn = (wn >> 3) + 2 * j + (lane >> 4);
                uint32_t t4[4];
                ldsm_x4_t(t4, bb + kl * 384 + ((cn ^ (kl & 7)) << 4));
                bfr[2 * j][0] = t4[0]; bfr[2 * j][1] = t4[1];
                bfr[2 * j + 1][0] = t4[2]; bfr[2 * j + 1][1] = t4[3];
            }
#pragma unroll
            for (int fi = 0; fi < 2; fi++)
#pragma unroll
                for (int nj = 0; nj < 6; nj++)
                    mma_bf16(acc[fi][nj], af[fi], bfr[nj]);
        }
        __syncthreads();
    }

#pragma unroll
    for (int fi = 0; fi < 2; fi++) {
        int rl = wm + fi * 16 + g;
        int rh = rl + 8;
        int tokl = win_row_to_tok(m0 + rl);
        int tokh = win_row_to_tok(m0 + rh);
#pragma unroll
        for (int nj = 0; nj < 6; nj++) {
            int col = wn + nj * 8 + q2;
            float bi0 = pbias[col], bi1 = pbias[col + 1];
            float2 xl = *(const float2*)&x[(size_t)tokl * C + col];
            float2 xh = *(const float2*)&x[(size_t)tokh * C + col];
            *(float2*)&x1[(size_t)tokl * C + col] =
                make_float2(acc[fi][nj][0] + bi0 + xl.x, acc[fi][nj][1] + bi1 + xl.y);
            *(float2*)&x1[(size_t)tokh * C + col] =
                make_float2(acc[fi][nj][2] + bi0 + xh.x, acc[fi][nj][3] + bi1 + xh.y);
        }
    }
}

// ---------------- fused MLP + LN2 (R10, frozen) ----------------------------
#define MLP_SMEM 223232
#define X1W 196

__device__ __forceinline__ void mlp_gemm_inner(uint32_t aBase, uint32_t sbBase,
                                               const __nv_bfloat16* __restrict__ Wg,
                                               int rstride, int rowbase, int coloff,
                                               int wm, int wn, int tid, int lane,
                                               float acc[2][6][4]) {
    auto issueW = [&](int s, int buf) {
#pragma unroll
        for (int j = 0; j < 2; j++) {
            int i = tid + j * 512;
            if (i < 768) {
                int kl = i / 24, cch = i % 24;
                cpasync16(sbBase + buf * 12288 + kl * 384 + ((cch ^ (kl & 7)) << 4),
                          Wg + (size_t)(rowbase + s * 32 + kl) * rstride + coloff + cch * 8);
            }
        }
        asm volatile("cp.async.commit_group;" ::: "memory");
    };

    issueW(0, 0);
    for (int s = 0; s < 6; s++) {
        if (s < 5) {
            issueW(s + 1, (s + 1) & 1);
            asm volatile("cp.async.wait_group 1;" ::: "memory");
        } else {
            asm volatile("cp.async.wait_group 0;" ::: "memory");
        }
        __syncthreads();
        uint32_t bb = sbBase + (s & 1) * 12288;
#pragma unroll
        for (int t = 0; t < 2; t++) {
            int kk = s * 2 + t;
            uint32_t af[2][4];
#pragma unroll
            for (int fi = 0; fi < 2; fi++) {
                int row = wm + fi * 16 + (lane & 7) + 8 * ((lane >> 3) & 1);
                int ch  = 2 * kk + (lane >> 4);
                ldsm_x4(af[fi], aBase + row * 384 + ((ch ^ (row & 7)) << 4));
            }
            uint32_t bfr[6][2];
#pragma unroll
            for (int j = 0; j < 3; j++) {
                int kl = t * 16 + (lane & 7) + 8 * ((lane >> 3) & 1);
                int cn = (wn >> 3) + 2 * j + (lane >> 4);
                uint32_t t4[4];
                ldsm_x4_t(t4, bb + kl * 384 + ((cn ^ (kl & 7)) << 4));
                bfr[2 * j][0] = t4[0]; bfr[2 * j][1] = t4[1];
                bfr[2 * j + 1][0] = t4[2]; bfr[2 * j + 1][1] = t4[3];
            }
#pragma unroll
            for (int fi = 0; fi < 2; fi++)
#pragma unroll
                for (int nj = 0; nj < 6; nj++)
                    mma_bf16(acc[fi][nj], af[fi], bfr[nj]);
        }
        __syncthreads();
    }
}

__global__ __launch_bounds__(512) void mlp_kernel(const float* __restrict__ x1,
                                                  const float* __restrict__ n2s,
                                                  const float* __restrict__ n2b,
                                                  const __nv_bfloat16* __restrict__ w1,
                                                  const float* __restrict__ b1,
                                                  const __nv_bfloat16* __restrict__ w2,
                                                  const float* __restrict__ b2,
                                                  float* __restrict__ out) {
    extern __shared__ char sm[];
    float* sX1 = (float*)sm;
    char* sXn_p = sm + 100352;
    char* sH_p  = sm + 149504;
    uint32_t sx1b = smem_u32(sm);
    uint32_t sxn  = sx1b + 100352;
    uint32_t shb  = sx1b + 149504;
    uint32_t sbb  = sx1b + 198656;

    int tid = threadIdx.x;
    int wid = tid >> 5, lane = tid & 31;
    int m0 = blockIdx.x * 128;
    int wm = (wid & 3) * 32;
    int wn = (wid >> 2) * 48;
    int g = lane >> 2, q2 = (lane & 3) * 2;

#pragma unroll
    for (int j = 0; j < 12; j++) {
        int i = tid + j * 512;
        int r = i / 48, cc = i % 48;
        cpasync16(sx1b + r * (X1W * 4) + cc * 16, x1 + (size_t)(m0 + r) * C + cc * 4);
    }
    asm volatile("cp.async.commit_group;" ::: "memory");
    asm volatile("cp.async.wait_group 0;" ::: "memory");
    __syncthreads();

    {
        const float2* sp = (const float2*)n2s;
        const float2* bp = (const float2*)n2b;
        float2 sg[3], bg[3];
#pragma unroll
        for (int i = 0; i < 3; i++) {
            sg[i] = sp[lane + i * 32];
            bg[i] = bp[lane + i * 32];
        }
#pragma unroll
        for (int rr = 0; rr < 8; rr++) {
            int row = wid * 8 + rr;
            const float2* rp = (const float2*)(sX1 + row * X1W);
            float2 v[3];
            float sum = 0.f, sq = 0.f;
#pragma unroll
            for (int i = 0; i < 3; i++) {
                v[i] = rp[lane + i * 32];
                sum += v[i].x + v[i].y;
                sq  += v[i].x * v[i].x + v[i].y * v[i].y;
            }
#pragma unroll
            for (int o = 16; o > 0; o >>= 1) {
                sum += __shfl_xor_sync(0xffffffffu, sum, o);
                sq  += __shfl_xor_sync(0xffffffffu, sq, o);
            }
            float mean = sum * (1.f / C);
            float var  = sq * (1.f / C) - mean * mean;
            float rstd = rsqrtf(var + 1e-5f);
#pragma unroll
            for (int i = 0; i < 3; i++) {
                int c2 = lane + i * 32;
                uint32_t val = packbf((v[i].x - mean) * rstd * sg[i].x + bg[i].x,
                                      (v[i].y - mean) * rstd * sg[i].y + bg[i].y);
                int ch = c2 >> 2;
                *(uint32_t*)(sXn_p + row * 384 + ((ch ^ (row & 7)) << 4) + (c2 & 3) * 4) = val;
            }
        }
    }
    __syncthreads();

    float acc2[2][6][4];
#pragma unroll
    for (int i = 0; i < 2; i++)
#pragma unroll
        for (int j = 0; j < 6; j++)
#pragma unroll
            for (int q = 0; q < 4; q++) acc2[i][j][q] = 0.f;

    for (int c = 0; c < 4; c++) {
        float acc1[2][6][4];
#pragma unroll
        for (int i = 0; i < 2; i++)
#pragma unroll
            for (int j = 0; j < 6; j++)
#pragma unroll
                for (int q = 0; q < 4; q++) acc1[i][j][q] = 0.f;
        mlp_gemm_inner(sxn, sbb, w1, 4 * C, 0, c * 192, wm, wn, tid, lane, acc1);

        const float is2 = 0.70710678118654752f;
#pragma unroll
        for (int fi = 0; fi < 2; fi++) {
            int rl = wm + fi * 16 + g;
            int rh = rl + 8;
#pragma unroll
            for (int nj = 0; nj < 6; nj++) {
                int colL = wn + nj * 8 + q2;
                int gcol = c * 192 + colL;
                float bi0 = b1[gcol], bi1 = b1[gcol + 1];
                float v00 = acc1[fi][nj][0] + bi0;
                float v01 = acc1[fi][nj][1] + bi1;
                float v10 = acc1[fi][nj][2] + bi0;
                float v11 = acc1[fi][nj][3] + bi1;
                v00 = 0.5f * v00 * (1.f + erff(v00 * is2));
                v01 = 0.5f * v01 * (1.f + erff(v01 * is2));
                v10 = 0.5f * v10 * (1.f + erff(v10 * is2));
                v11 = 0.5f * v11 * (1.f + erff(v11 * is2));
                int chh = colL >> 3;
                *(uint32_t*)(sH_p + rl * 384 + ((chh ^ (rl & 7)) << 4) + q2 * 2) = packbf(v00, v01);
                *(uint32_t*)(sH_p + rh * 384 + ((chh ^ (rh & 7)) << 4) + q2 * 2) = packbf(v10, v11);
            }
        }
        __syncthreads();

        mlp_gemm_inner(shb, sbb, w2, C, c * 192, 0, wm, wn, tid, lane, acc2);
    }

#pragma unroll
    for (int fi = 0; fi < 2; fi++) {
        int rl = wm + fi * 16 + g;
        int rh = rl + 8;
        int ml = m0 + rl, mh = m0 + rh;
#pragma unroll
        for (int nj = 0; nj < 6; nj++) {
            int col = wn + nj * 8 + q2;
            float bi0 = b2[col], bi1 = b2[col + 1];
            float xl0 = sX1[rl * X1W + col],     xl1 = sX1[rl * X1W + col + 1];
            float xh0 = sX1[rh * X1W + col],     xh1 = sX1[rh * X1W + col + 1];
            *(float2*)&out[(size_t)ml * C + col] =
                make_float2(acc2[fi][nj][0] + bi0 + xl0, acc2[fi][nj][1] + bi1 + xl1);
            *(float2*)&out[(size_t)mh * C + col] =
                make_float2(acc2[fi][nj][2] + bi0 + xh0, acc2[fi][nj][3] + bi1 + xh1);
        }
    }
}

// ---------------- launch ---------------------------------------------------
extern "C" void kernel_launch(void* const* d_in, const int* in_sizes, int n_in,
                              void* d_out, int out_size) {
    const float* x      = (const float*)d_in[0];
    const float* qkv_w  = (const float*)d_in[1];
    const float* qkv_b  = (const float*)d_in[2];
    const float* proj_w = (const float*)d_in[3];
    const float* proj_b = (const float*)d_in[4];
    const float* rpb    = (const float*)d_in[5];
    const float* n1s    = (const float*)d_in[6];
    const float* n1b    = (const float*)d_in[7];
    const float* n2s    = (const float*)d_in[8];
    const float* n2b    = (const float*)d_in[9];
    const float* w1     = (const float*)d_in[10];
    const float* b1     = (const float*)d_in[11];
    const float* w2     = (const float*)d_in[12];
    const float* b2     = (const float*)d_in[13];
    float* out = (float*)d_out;

    __nv_bfloat16 *xw, *qkv, *wqkv, *wproj, *ww1, *ww2;
    float *x1, *abias;
    cudaGetSymbolAddress((void**)&xw,    g_xw);
    cudaGetSymbolAddress((void**)&qkv,   g_qkv);
    cudaGetSymbolAddress((void**)&x1,    g_x1);
    cudaGetSymbolAddress((void**)&wqkv,  g_wqkv);
    cudaGetSymbolAddress((void**)&wproj, g_wproj);
    cudaGetSymbolAddress((void**)&ww1,   g_w1);
    cudaGetSymbolAddress((void**)&ww2,   g_w2);
    cudaGetSymbolAddress((void**)&abias, g_abias);

    cudaFuncSetAttribute(qkv_gemm,        cudaFuncAttributeMaxDynamicSharedMemorySize, QKV_SMEM);
    cudaFuncSetAttribute(attnproj_kernel, cudaFuncAttributeMaxDynamicSharedMemorySize, MK_SMEM);
    cudaFuncSetAttribute(mlp_kernel,      cudaFuncAttributeMaxDynamicSharedMemorySize, MLP_SMEM);

    // 1. merged prologue: LN1 (+shift/window gather) and weight/abias prep
    prologue_kernel<<<LN_BLOCKS + PREP_BLOCKS, 256>>>(x, n1s, n1b,
                                                      qkv_w, proj_w, w1, w2, rpb,
                                                      xw, wqkv, wproj, ww1, ww2, abias);

    // 2. QKV GEMM -> bf16
    qkv_gemm<<<dim3((3 * C) / GBN, NTOK / GBM), 256, QKV_SMEM>>>(xw, wqkv, qkv_b, qkv,
                                                                 NTOK, 3 * C, C);

    // 3. attention + proj + residual -> x1 (fp32, token order)
    attnproj_kernel<<<NTOK / 128, 512, MK_SMEM>>>(qkv, abias, wproj, proj_b, x, x1);

    // 4. fused LN2 + MLP + residual -> out
    mlp_kernel<<<NTOK / 128, 512, MLP_SMEM>>>(x1, n2s, n2b, ww1, b1, ww2, b2, out);
}